// round 13
// baseline (speedup 1.0000x reference)
#include <cuda_runtime.h>
#include <cuda_bf16.h>
#include <math.h>
#include <stdint.h>

// Problem constants
#define Bc  4
#define Tc  4096
#define Dc  1024
#define Hc  16
#define HDc 64
#define Kc  32

#define SKS 8       // split-K for spec GEMM (slab 128)
#define SKZ 16      // split-K for Z GEMM   (slab 64)

// ---------------- scratch (static device arrays) ----------------
__device__ float g_xm[Bc * 1024];                // sum_t x
__device__ float g_qm[Bc * 1024];                // xm @ Wq^T (unnormalized)
__device__ float g_spec_p[SKS * 128 * 3072];     // spec GEMM partials
__device__ float g_Zp[SKZ * 128 * 1024];         // Z GEMM partials
__device__ __nv_bfloat16 g_xshi[128 * 1024], g_xslo[128 * 1024];
__device__ __nv_bfloat16 g_wqhi[3 * 1024 * 1024], g_wqlo[3 * 1024 * 1024];
__device__ __nv_bfloat16 g_wohi[1024 * 1024], g_wolo[1024 * 1024];
__device__ __nv_bfloat16 g_wshi[128 * 1024], g_wslo[128 * 1024];
__device__ __nv_bfloat16 g_sbhi[Bc * Tc * 32], g_sblo[Bc * Tc * 32];
__device__ __nv_bfloat16 g_Zthi[Bc * 1024 * 32], g_Ztlo[Bc * 1024 * 32];

__device__ __forceinline__ uint32_t smem_u32(const void* p) {
    uint32_t a;
    asm("{ .reg .u64 t; cvta.to.shared.u64 t, %1; cvt.u32.u64 %0, t; }"
        : "=r"(a) : "l"(p));
    return a;
}
__device__ __forceinline__ uint2 pack_hilo4(const float* v, bool lo) {
    __nv_bfloat16 h[4];
#pragma unroll
    for (int j = 0; j < 4; j++) {
        __nv_bfloat16 hh = __float2bfloat16_rn(v[j]);
        h[j] = lo ? __float2bfloat16_rn(v[j] - __bfloat162float(hh)) : hh;
    }
    uint2 r;
    r.x = (uint32_t)__bfloat16_as_ushort(h[0]) |
          ((uint32_t)__bfloat16_as_ushort(h[1]) << 16);
    r.y = (uint32_t)__bfloat16_as_ushort(h[2]) |
          ((uint32_t)__bfloat16_as_ushort(h[3]) << 16);
    return r;
}
__device__ __forceinline__ uint32_t pack2(float a, float b) {
    return (uint32_t)__bfloat16_as_ushort(__float2bfloat16_rn(a)) |
           ((uint32_t)__bfloat16_as_ushort(__float2bfloat16_rn(b)) << 16);
}
__device__ __forceinline__ float bf16lo(float v) {
    return v - __bfloat162float(__float2bfloat16_rn(v));
}

#define MMA_OP(d, A, b0, b1)                                                  \
    asm volatile("mma.sync.aligned.m16n8k16.row.col.f32.bf16.bf16.f32 "       \
                 "{%0,%1,%2,%3},{%4,%5,%6,%7},{%8,%9},{%0,%1,%2,%3};"         \
                 : "+f"(d[0]), "+f"(d[1]), "+f"(d[2]), "+f"(d[3])             \
                 : "r"(A[0]), "r"(A[1]), "r"(A[2]), "r"(A[3]),                \
                   "r"(b0), "r"(b1))

#define LDSM4(r, addr)                                                        \
    asm volatile("ldmatrix.sync.aligned.m8n8.x4.shared.b16 {%0,%1,%2,%3},[%4];"\
        : "=r"((r)[0]), "=r"((r)[1]), "=r"((r)[2]), "=r"((r)[3]) : "r"(addr))

// ---------------------------------------------------------------------------
// xs via HMMA: blocks [0,64): (b, dtile of 64 d) compute
//   xs[b*32+k][dblk+n] = sum_t sb[b][t][k] * x[b][t][dblk+n]   (bf16 3-split)
//   + xm[b][d-slice] (exact fp32) + sb bf16 split (dt==0 blocks).
// Transpose-on-store: bf16 tiles written [k][t] / [d][t], pitch 144B, then
// the PROVEN non-trans ldmatrix recipe applies (mma k-dim = t).
// Blocks [64, 64+4096): Wqkv/Wout bf16 hi/lo split.
// ---------------------------------------------------------------------------
#define XROW 144
__global__ __launch_bounds__(256) void xs_mma_kernel(
    const float* __restrict__ x, const float* __restrict__ sb,
    const float* __restrict__ Wqkv, const float* __restrict__ Wout)
{
    const int tid = threadIdx.x;
    if ((int)blockIdx.x >= 64) {
        int i = (blockIdx.x - 64) * 256 + tid;
        const int NQ4 = 3 * 1024 * 1024 / 4;
        const float* src;
        __nv_bfloat16 *hi, *lo;
        int j;
        if (i < NQ4) { src = Wqkv; hi = g_wqhi; lo = g_wqlo; j = i; }
        else { src = Wout; hi = g_wohi; lo = g_wolo; j = i - NQ4;
               if (j >= 1024 * 1024 / 4) return; }
        float4 v = ((const float4*)src)[j];
        float vv[4] = { v.x, v.y, v.z, v.w };
        ((uint2*)hi)[j] = pack_hilo4(vv, false);
        ((uint2*)lo)[j] = pack_hilo4(vv, true);
        return;
    }

    const int b = blockIdx.x >> 4, dt = blockIdx.x & 15;
    const int dblk = dt * 64;
    const int wid = tid >> 5, lane = tid & 31;
    const int wm = wid & 1, wn = wid >> 1;        // warp tile: m16 x n16

    __shared__ __align__(16) char sm[27648];      // A(hi,lo) 32x144 ; B(hi,lo) 64x144
    __shared__ float xmred[8][64];
    const uint32_t sbase = smem_u32(sm);
    const int XA_HI = 0, XA_LO = 4608, XB_HI = 9216, XB_LO = 18432;
    unsigned short* sm16 = (unsigned short*)sm;

    float acc[2][4];
#pragma unroll
    for (int i = 0; i < 2; i++)
#pragma unroll
        for (int q = 0; q < 4; q++) acc[i][q] = 0.f;
    float xm0 = 0.f, xm1 = 0.f;
    const int d2 = lane * 2;

    for (int it = 0; it < 64; it++) {
        const int t0 = it * 64;
        // --- sb tile 64t x 32k -> transposed [k][t] hi/lo ---
#pragma unroll
        for (int i = 0; i < 2; i++) {
            int idx = tid + i * 256;
            int tt = idx >> 3, k4 = (idx & 7) * 4;
            size_t gofs = ((size_t)b * Tc + t0 + tt) * 32 + k4;
            float4 v = *(const float4*)(sb + gofs);
            float vv[4] = { v.x, v.y, v.z, v.w };
#pragma unroll
            for (int j = 0; j < 4; j++) {
                __nv_bfloat16 hh = __float2bfloat16_rn(vv[j]);
                __nv_bfloat16 ll = __float2bfloat16_rn(vv[j] - __bfloat162float(hh));
                sm16[(XA_HI + (k4 + j) * XROW) / 2 + tt] = __bfloat16_as_ushort(hh);
                sm16[(XA_LO + (k4 + j) * XROW) / 2 + tt] = __bfloat16_as_ushort(ll);
            }
            if (dt == 0) {
                ((uint2*)g_sbhi)[gofs / 4] = pack_hilo4(vv, false);
                ((uint2*)g_sblo)[gofs / 4] = pack_hilo4(vv, true);
            }
        }
        // --- x tile 64t x 64d -> transposed [d][t] hi/lo, paired-t U32 ---
#pragma unroll
        for (int i = 0; i < 4; i++) {
            int tp = wid + i * 8;                 // t-pair 0..31
            const float* xp = x + ((size_t)b * Tc + t0 + tp * 2) * Dc + dblk + d2;
            float2 a0 = *(const float2*)xp;
            float2 a1 = *(const float2*)(xp + Dc);
            xm0 += a0.x + a1.x;
            xm1 += a0.y + a1.y;
            *(uint32_t*)(sm + XB_HI + d2 * XROW + tp * 4) = pack2(a0.x, a1.x);
            *(uint32_t*)(sm + XB_LO + d2 * XROW + tp * 4) =
                pack2(bf16lo(a0.x), bf16lo(a1.x));
            *(uint32_t*)(sm + XB_HI + (d2 + 1) * XROW + tp * 4) = pack2(a0.y, a1.y);
            *(uint32_t*)(sm + XB_LO + (d2 + 1) * XROW + tp * 4) =
                pack2(bf16lo(a0.y), bf16lo(a1.y));
        }
        __syncthreads();
        // --- MMA: K=64 (t) in 4 ks steps ---
#pragma unroll
        for (int ks = 0; ks < 4; ks++) {
            uint32_t ah[4], al[4], bh[4], bl[4];
            uint32_t aa = sbase + XA_HI + (wm * 16 + (lane & 15)) * XROW
                          + ks * 32 + ((lane >> 4) & 1) * 16;
            LDSM4(ah, aa);
            LDSM4(al, aa + (XA_LO - XA_HI));
            uint32_t bb = sbase + XB_HI
                          + (wn * 16 + ((lane >> 4) & 1) * 8 + (lane & 7)) * XROW
                          + ks * 32 + ((lane >> 3) & 1) * 16;
            LDSM4(bh, bb);
            LDSM4(bl, bb + (XB_LO - XB_HI));
            MMA_OP(acc[0], ah, bh[0], bh[1]);
            MMA_OP(acc[1], ah, bh[2], bh[3]);
            MMA_OP(acc[0], ah, bl[0], bl[1]);
            MMA_OP(acc[1], ah, bl[2], bl[3]);
            MMA_OP(acc[0], al, bh[0], bh[1]);
            MMA_OP(acc[1], al, bh[2], bh[3]);
        }
        __syncthreads();
    }

    // xm reduce (exact fp32)
    xmred[wid][d2] = xm0;
    xmred[wid][d2 + 1] = xm1;
    __syncthreads();
    if (tid < 64) {
        float s = 0.f;
#pragma unroll
        for (int w = 0; w < 8; w++) s += xmred[w][tid];
        g_xm[b * 1024 + dblk + tid] = s;
    }

    // epilogue: xs -> bf16 hi/lo, rows = b*32 + m (k_idx), cols = dblk + n (d)
    const int row = b * 32 + wm * 16 + (lane >> 2);
#pragma unroll
    for (int nf = 0; nf < 2; nf++) {
        int n = dblk + wn * 16 + nf * 8 + (lane & 3) * 2;
        *(uint32_t*)(g_xshi + (size_t)row * 1024 + n) =
            pack2(acc[nf][0], acc[nf][1]);
        *(uint32_t*)(g_xslo + (size_t)row * 1024 + n) =
            pack2(bf16lo(acc[nf][0]), bf16lo(acc[nf][1]));
        *(uint32_t*)(g_xshi + (size_t)(row + 8) * 1024 + n) =
            pack2(acc[nf][2], acc[nf][3]);
        *(uint32_t*)(g_xslo + (size_t)(row + 8) * 1024 + n) =
            pack2(bf16lo(acc[nf][2]), bf16lo(acc[nf][3]));
    }
}

// ---------------------------------------------------------------------------
// HMMA GEMM NT, M=128, split-K, 3-product bf16 split + fused qm GEMV blocks.
// ---------------------------------------------------------------------------
#define KT      32
#define RB      80
#define TILE_B  (128 * RB)
#define STAGE_B (4 * TILE_B)

__global__ void __launch_bounds__(256, 2) gemm_mma_sk(
    const __nv_bfloat16* __restrict__ Ahi, const __nv_bfloat16* __restrict__ Alo,
    const __nv_bfloat16* __restrict__ Bhi, const __nv_bfloat16* __restrict__ Blo,
    float* __restrict__ Cp, int N, int kPerSplit, int nGemm,
    const float* __restrict__ WqF)
{
    const int tid = threadIdx.x;
    if ((int)blockIdx.x >= nGemm) {
        const int w = (blockIdx.x - nGemm) * 8 + (tid >> 5);
        const int lane = tid & 31;
        const int b = w >> 10, o = w & 1023;
        const float4* xm = (const float4*)(g_xm + b * 1024);
        const float4* wr = (const float4*)(WqF + (size_t)o * 1024);
        float s = 0.f;
#pragma unroll
        for (int j = 0; j < 8; j++) {
            float4 a = xm[lane + j * 32];
            float4 c = wr[lane + j * 32];
            s = fmaf(a.x, c.x, s); s = fmaf(a.y, c.y, s);
            s = fmaf(a.z, c.z, s); s = fmaf(a.w, c.w, s);
        }
#pragma unroll
        for (int off = 16; off; off >>= 1)
            s += __shfl_down_sync(0xffffffffu, s, off);
        if (lane == 0) g_qm[b * 1024 + o] = s;
        return;
    }

    extern __shared__ char smem[];
    const int Kd = 1024;
    const uint32_t sbase = smem_u32(smem);
    const int wid = tid >> 5, lane = tid & 31;
    const int nCols = N >> 7;
    const int col0 = (blockIdx.x % nCols) * 128;
    const int kb = (blockIdx.x / nCols) * kPerSplit;
    const int wm = wid >> 2, wn = wid & 3;

    const __nv_bfloat16* s0 = Ahi + kb;
    const __nv_bfloat16* s1 = Alo + kb;
    const __nv_bfloat16* s2 = Bhi + (size_t)col0 * Kd + kb;
    const __nv_bfloat16* s3 = Blo + (size_t)col0 * Kd + kb;

    const int e0 = tid, e1 = tid + 256;
    const int r0c = e0 >> 2, c0c = e0 & 3;
    const int r1c = e1 >> 2, c1c = e1 & 3;

#define LOAD_STAGE(kt, buf)                                                   \
    do {                                                                      \
        uint32_t db = sbase + (buf) * STAGE_B;                                \
        const __nv_bfloat16* srcs[4] = { s0, s1, s2, s3 };                    \
        _Pragma("unroll")                                                     \
        for (int a = 0; a < 4; a++) {                                         \
            const char* g0 = (const char*)(srcs[a] + (size_t)r0c * Kd + (kt) * KT) + c0c * 16; \
            const char* g1 = (const char*)(srcs[a] + (size_t)r1c * Kd + (kt) * KT) + c1c * 16; \
            uint32_t p0 = db + a * TILE_B + r0c * RB + c0c * 16;              \
            uint32_t p1 = db + a * TILE_B + r1c * RB + c1c * 16;              \
            asm volatile("cp.async.cg.shared.global [%0],[%1],16;" :: "r"(p0), "l"(g0)); \
            asm volatile("cp.async.cg.shared.global [%0],[%1],16;" :: "r"(p1), "l"(g1)); \
        }                                                                     \
        asm volatile("cp.async.commit_group;");                               \
    } while (0)

    float acc[4][4][4];
#pragma unroll
    for (int i = 0; i < 4; i++)
#pragma unroll
        for (int j = 0; j < 4; j++)
#pragma unroll
            for (int q = 0; q < 4; q++) acc[i][j][q] = 0.f;

    LOAD_STAGE(0, 0);
    int buf = 0;
    const int nTiles = kPerSplit / KT;

    for (int kt = 0; kt < nTiles; kt++) {
        asm volatile("cp.async.wait_group 0;");
        __syncthreads();
        if (kt + 1 < nTiles) LOAD_STAGE(kt + 1, buf ^ 1);

        const uint32_t db = sbase + buf * STAGE_B;
#pragma unroll
        for (int ks = 0; ks < 2; ks++) {
            uint32_t rah[4][4], ral[4][4];
#pragma unroll
            for (int mf = 0; mf < 4; mf++) {
                int r = wm * 64 + mf * 16 + (lane & 15);
                uint32_t ad = db + r * RB + ks * 32 + ((lane >> 4) & 1) * 16;
                LDSM4(rah[mf], ad);
                LDSM4(ral[mf], ad + TILE_B);
            }
            uint32_t rbh[2][4], rbl[2][4];
#pragma unroll
            for (int np = 0; np < 2; np++) {
                int r = wn * 32 + (np * 2 + (lane >> 4)) * 8 + (lane & 7);
                uint32_t bd = db + 2 * TILE_B + r * RB + ks * 32 + ((lane >> 3) & 1) * 16;
                LDSM4(rbh[np], bd);
                LDSM4(rbl[np], bd + TILE_B);
            }
#pragma unroll
            for (int mf = 0; mf < 4; mf++)
#pragma unroll
                for (int nf = 0; nf < 4; nf++)
                    MMA_OP(acc[mf][nf], rah[mf], rbh[nf >> 1][(nf & 1) * 2],
                           rbh[nf >> 1][(nf & 1) * 2 + 1]);
#pragma unroll
            for (int mf = 0; mf < 4; mf++)
#pragma unroll
                for (int nf = 0; nf < 4; nf++)
                    MMA_OP(acc[mf][nf], rah[mf], rbl[nf >> 1][(nf & 1) * 2],
                           rbl[nf >> 1][(nf & 1) * 2 + 1]);
#pragma unroll
            for (int mf = 0; mf < 4; mf++)
#pragma unroll
                for (int nf = 0; nf < 4; nf++)
                    MMA_OP(acc[mf][nf], ral[mf], rbh[nf >> 1][(nf & 1) * 2],
                           rbh[nf >> 1][(nf & 1) * 2 + 1]);
        }
        __syncthreads();
        buf ^= 1;
    }

    float* C = Cp + (size_t)(blockIdx.x / nCols) * 128 * N;
    const int mrow = lane >> 2, ncol = (lane & 3) * 2;
#pragma unroll
    for (int mf = 0; mf < 4; mf++) {
#pragma unroll
        for (int nf = 0; nf < 4; nf++) {
            int r  = wm * 64 + mf * 16 + mrow;
            int cc = col0 + wn * 32 + nf * 8 + ncol;
            *(float2*)(C + (size_t)r * N + cc) =
                make_float2(acc[mf][nf][0], acc[mf][nf][1]);
            *(float2*)(C + (size_t)(r + 8) * N + cc) =
                make_float2(acc[mf][nf][2], acc[mf][nf][3]);
        }
    }
#undef LOAD_STAGE
}

// ---------------------------------------------------------------------------
// Fused (512 threads): blocks 0..127: reduce spec partials + 16 ODEs +
// ws2 bf16 split. Blocks 128..191: pulse MLP.
// ---------------------------------------------------------------------------
__global__ __launch_bounds__(512) void soliton_pulse_kernel(
    const float* __restrict__ d_a, const float* __restrict__ d_b,
    const float* __restrict__ filt,
    const float* __restrict__ W1, const float* __restrict__ b1,
    const float* __restrict__ W2, const float* __restrict__ b2,
    float* __restrict__ out_resp, float* __restrict__ out_pulse)
{
    const int tid = threadIdx.x;
    if (blockIdx.x < 128) {
        const int m = blockIdx.x;
        const int b = m >> 5, k = m & 31;
        __shared__ __align__(16) float srow[3072];
        __shared__ float resp_s[16];

        const size_t SPL4 = 128 * 3072 / 4;
        const size_t rb4 = (size_t)m * 768;
        for (int idx = tid; idx < 768; idx += 512) {
            float4 a = make_float4(0.f, 0.f, 0.f, 0.f);
#pragma unroll
            for (int s = 0; s < SKS; s++) {
                float4 v = ((const float4*)g_spec_p)[s * SPL4 + rb4 + idx];
                a.x += v.x; a.y += v.y; a.z += v.z; a.w += v.w;
            }
            ((float4*)srow)[idx] = a;
        }
        __syncthreads();

        if (tid < 16) {
            const int h = tid;
            float dot = 0.f;
#pragma unroll
            for (int d = 0; d < 64; d++)
                dot = fmaf(srow[h * 64 + d], srow[1024 + h * 64 + d], dot);

            float f = 1.f / (1.f + expf(-filt[h * 32 + k]));
            float stim = dot * 0.125f * f;

            const float a = d_a[0], bb = d_b[0];
            float scale = fmaxf(fabsf(stim), 1e-6f);
            float sn = stim / scale;
            float I = (fabsf(stim) > 0.5f) ? sn : sn * 0.1f;
            float v = 0.f, w = 0.f;
            const float dt = 0.2f;
#pragma unroll
            for (int s = 0; s < 5; s++) {
                float dv = v - v * v * v * (1.f / 3.f) - w + I;
                float dw = (v + a - bb * w) * 10.f;
                v = fminf(fmaxf(v + dt * dv, -3.f), 3.f);
                w = fminf(fmaxf(w + dt * dw, -3.f), 3.f);
            }
            float resp = v * scale;
            resp_s[h] = resp;
            out_resp[b * 512 + h * 32 + k] = resp;
        }
        __syncthreads();

        if (tid < 256) {
            const int h = tid >> 4;
            float r = resp_s[h];
            float4 vv = ((const float4*)srow)[512 + tid];
            float wv[4] = { r * vv.x, r * vv.y, r * vv.z, r * vv.w };
            ((uint2*)g_wshi)[(size_t)m * 256 + tid] = pack_hilo4(wv, false);
            ((uint2*)g_wslo)[(size_t)m * 256 + tid] = pack_hilo4(wv, true);
        }
    } else {
        const int bh = blockIdx.x - 128;
        const int b = bh >> 4, h = bh & 15;
        if (tid >= 32) return;
        const float* qm = g_qm + b * 1024 + h * 64;
        float acc = b1[tid];
#pragma unroll
        for (int dd = 0; dd < 64; dd++)
            acc = fmaf(qm[dd] * (1.0f / Tc), W1[tid * 64 + dd], acc);
        float h1 = acc / (1.f + expf(-acc));
        float pp = h1 * W2[tid];
#pragma unroll
        for (int off = 16; off; off >>= 1)
            pp += __shfl_down_sync(0xffffffffu, pp, off);
        if (tid == 0) {
            float xv = pp + b2[0];
            float sp = (xv > 20.f) ? xv : log1pf(expf(xv));
            out_pulse[bh] = 4.0f + sp;
        }
    }
}

// ---------------------------------------------------------------------------
// Reduce Z partials -> Zt (transposed, bf16 hi/lo): Zt[b][d][k] = Z[b*32+k][d]
// ---------------------------------------------------------------------------
__global__ void reduce_Zt()
{
    int i = blockIdx.x * blockDim.x + threadIdx.x;
    if (i >= 32768) return;
    const int m = i >> 8, d0 = (i & 255) * 4;
    const int b = m >> 5, k = m & 31;
    float4 a = make_float4(0.f, 0.f, 0.f, 0.f);
#pragma unroll
    for (int s = 0; s < SKZ; s++) {
        float4 v = ((const float4*)g_Zp)[(size_t)s * 32768 + i];
        a.x += v.x; a.y += v.y; a.z += v.z; a.w += v.w;
    }
    float vv[4] = { a.x, a.y, a.z, a.w };
#pragma unroll
    for (int j = 0; j < 4; j++) {
        __nv_bfloat16 hh = __float2bfloat16_rn(vv[j]);
        __nv_bfloat16 ll = __float2bfloat16_rn(vv[j] - __bfloat162float(hh));
        size_t oi = ((size_t)b * 1024 + d0 + j) * 32 + k;
        g_Zthi[oi] = hh;
        g_Ztlo[oi] = ll;
    }
}

// ---------------------------------------------------------------------------
// out HMMA: out[b, t0:t0+128, d0:d0+128] = sb[b,t,:] @ Zt[b,d,:]^T  (K=32)
// ---------------------------------------------------------------------------
__global__ __launch_bounds__(256, 2) void out_mma_kernel(float* __restrict__ out)
{
    __shared__ __align__(16) char smem[4 * TILE_B];
    const int tid = threadIdx.x, wid = tid >> 5, lane = tid & 31;
    const int t0 = blockIdx.x * 128, d0 = blockIdx.y * 128, b = blockIdx.z;
    const int wm = wid >> 2, wn = wid & 3;
    const uint32_t sbase = smem_u32(smem);

    {
        const char* srcs[4] = {
            (const char*)(g_sbhi + ((size_t)b * Tc + t0) * 32),
            (const char*)(g_sblo + ((size_t)b * Tc + t0) * 32),
            (const char*)(g_Zthi + ((size_t)b * 1024 + d0) * 32),
            (const char*)(g_Ztlo + ((size_t)b * 1024 + d0) * 32) };
#pragma unroll
        for (int a = 0; a < 4; a++) {
#pragma unroll
            for (int i = 0; i < 2; i++) {
                int e = tid + i * 256;
                int r = e >> 2, c = e & 3;
                uint4 v = *(const uint4*)(srcs[a] + (size_t)r * 64 + c * 16);
                *(uint4*)(smem + a * TILE_B + r * RB + c * 16) = v;
            }
        }
    }
    __syncthreads();

    float acc[4][4][4];
#pragma unroll
    for (int i = 0; i < 4; i++)
#pragma unroll
        for (int j = 0; j < 4; j++)
#pragma unroll
            for (int q = 0; q < 4; q++) acc[i][j][q] = 0.f;

#pragma unroll
    for (int ks = 0; ks < 2; ks++) {
        uint32_t rah[4][4], ral[4][4];
#pragma unroll
        for (int mf = 0; mf < 4; mf++) {
            int r = wm * 64 + mf * 16 + (lane & 15);
            uint32_t ad = sbase + r * RB + ks * 32 + ((lane >> 4) & 1) * 16;
            LDSM4(rah[mf], ad);
            LDSM4(ral[mf], ad + TILE_B);
        }
        uint32_t rbh[2][4], rbl[2][4];
#pragma unroll
        for (int np = 0; np < 2; np++) {
            int r = wn * 32 + (np * 2 + (lane >> 4)) * 8 + (lane & 7);
            uint32_t bd = sbase + 2 * TILE_B + r * RB + ks * 32 + ((lane >> 3) & 1) * 16;
            LDSM4(rbh[np], bd);
            LDSM4(rbl[np], bd + TILE_B);
        }
#pragma unroll
        for (int mf = 0; mf < 4; mf++)
#pragma unroll
            for (int nf = 0; nf < 4; nf++)
                MMA_OP(acc[mf][nf], rah[mf], rbh[nf >> 1][(nf & 1) * 2],
                       rbh[nf >> 1][(nf & 1) * 2 + 1]);
#pragma unroll
        for (int mf = 0; mf < 4; mf++)
#pragma unroll
            for (int nf = 0; nf < 4; nf++)
                MMA_OP(acc[mf][nf], rah[mf], rbl[nf >> 1][(nf & 1) * 2],
                       rbl[nf >> 1][(nf & 1) * 2 + 1]);
#pragma unroll
        for (int mf = 0; mf < 4; mf++)
#pragma unroll
            for (int nf = 0; nf < 4; nf++)
                MMA_OP(acc[mf][nf], ral[mf], rbh[nf >> 1][(nf & 1) * 2],
                       rbh[nf >> 1][(nf & 1) * 2 + 1]);
    }

    const int mrow = lane >> 2, ncol = (lane & 3) * 2;
#pragma unroll
    for (int mf = 0; mf < 4; mf++) {
#pragma unroll
        for (int nf = 0; nf < 4; nf++) {
            int r  = t0 + wm * 64 + mf * 16 + mrow;
            int cc = d0 + wn * 32 + nf * 8 + ncol;
            *(float2*)(out + ((size_t)b * Tc + r) * Dc + cc) =
                make_float2(acc[mf][nf][0], acc[mf][nf][1]);
            *(float2*)(out + ((size_t)b * Tc + r + 8) * Dc + cc) =
                make_float2(acc[mf][nf][2], acc[mf][nf][3]);
        }
    }
}

// ---------------------------------------------------------------------------
// Launch
// ---------------------------------------------------------------------------
extern "C" void kernel_launch(void* const* d_in, const int* in_sizes, int n_in,
                              void* d_out, int out_size)
{
    const float* x    = (const float*)d_in[0];
    const float* sb   = (const float*)d_in[1];
    const float* Wqkv = (const float*)d_in[2];
    const float* Wout = (const float*)d_in[3];
    const float* a    = (const float*)d_in[4];
    const float* b    = (const float*)d_in[5];
    const float* W1   = (const float*)d_in[6];
    const float* b1   = (const float*)d_in[7];
    const float* W2   = (const float*)d_in[8];
    const float* b2   = (const float*)d_in[9];
    const float* filt = (const float*)d_in[10];

    float* out       = (float*)d_out;
    float* out_pulse = out + (size_t)Bc * Tc * Dc;
    float* out_resp  = out_pulse + Bc * Hc;

    float *pspec_p, *pZp;
    cudaGetSymbolAddress((void**)&pspec_p, g_spec_p);
    cudaGetSymbolAddress((void**)&pZp, g_Zp);
    __nv_bfloat16 *pxshi, *pxslo, *pwqhi, *pwqlo, *pwohi, *pwolo, *pwshi, *pwslo;
    cudaGetSymbolAddress((void**)&pxshi, g_xshi);
    cudaGetSymbolAddress((void**)&pxslo, g_xslo);
    cudaGetSymbolAddress((void**)&pwqhi, g_wqhi);
    cudaGetSymbolAddress((void**)&pwqlo, g_wqlo);
    cudaGetSymbolAddress((void**)&pwohi, g_wohi);
    cudaGetSymbolAddress((void**)&pwolo, g_wolo);
    cudaGetSymbolAddress((void**)&pwshi, g_wshi);
    cudaGetSymbolAddress((void**)&pwslo, g_wslo);

    const int GEMM_SMEM = 2 * STAGE_B;
    cudaFuncSetAttribute(gemm_mma_sk, cudaFuncAttributeMaxDynamicSharedMemorySize,
                         GEMM_SMEM);

    // 1) xs via HMMA (+ xm + sb split + weight split, all fused)
    xs_mma_kernel<<<64 + 4096, 256>>>(x, sb, Wqkv, Wout);

    // 2) spec partials [HMMA split-K 8] ++ qm GEMV fused
    gemm_mma_sk<<<24 * SKS + 512, 256, GEMM_SMEM>>>(
        pxshi, pxslo, pwqhi, pwqlo, pspec_p, 3072, 1024 / SKS, 24 * SKS, Wqkv);

    // 3) spec reduce + soliton + ws2 split + pulse MLP
    soliton_pulse_kernel<<<128 + 64, 512>>>(a, b, filt, W1, b1, W2, b2,
                                            out_resp, out_pulse);

    // 4) Z partials [HMMA split-K 16] + reduce -> Zt bf16
    gemm_mma_sk<<<8 * SKZ, 256, GEMM_SMEM>>>(
        pwshi, pwslo, pwohi, pwolo, pZp, 1024, 1024 / SKZ, 8 * SKZ, Wqkv);
    reduce_Zt<<<(32768 + 255) / 256, 256>>>();

    // 5) out = sb @ Zt^T [HMMA, K=32]
    out_mma_kernel<<<dim3(Tc / 128, Dc / 128, Bc), 256>>>(out);
}

// round 14
// speedup vs baseline: 1.1450x; 1.1450x over previous
#include <cuda_runtime.h>
#include <cuda_bf16.h>
#include <math.h>
#include <stdint.h>

// Problem constants
#define Bc  4
#define Tc  4096
#define Dc  1024
#define Hc  16
#define HDc 64
#define Kc  32

#define NS1 32      // t-slices for xs build (128 t each)
#define SKS 8       // split-K for spec GEMM (slab 128)

// ---------------- scratch (static device arrays) ----------------
__device__ float g_xs_p[NS1 * 128 * 1024];       // xs partials
__device__ float g_xm_p[NS1 * Bc * 1024];        // xmean partials
__device__ float g_xm[Bc * 1024];                // sum_t x
__device__ float g_qm[Bc * 1024];                // xm @ Wq^T (unnormalized)
__device__ float g_spec_p[SKS * 128 * 3072];     // spec GEMM partials
__device__ __nv_bfloat16 g_xshi[128 * 1024], g_xslo[128 * 1024];
__device__ __nv_bfloat16 g_wqhi[3 * 1024 * 1024], g_wqlo[3 * 1024 * 1024];
__device__ __nv_bfloat16 g_wohi[1024 * 1024], g_wolo[1024 * 1024];
__device__ __nv_bfloat16 g_wshi[128 * 1024], g_wslo[128 * 1024];
__device__ __nv_bfloat16 g_sbhi[Bc * Tc * 32], g_sblo[Bc * Tc * 32];
__device__ __nv_bfloat16 g_Zthi[Bc * 1024 * 32], g_Ztlo[Bc * 1024 * 32];

__device__ __forceinline__ uint32_t smem_u32(const void* p) {
    uint32_t a;
    asm("{ .reg .u64 t; cvta.to.shared.u64 t, %1; cvt.u32.u64 %0, t; }"
        : "=r"(a) : "l"(p));
    return a;
}
__device__ __forceinline__ uint2 pack_hilo4(const float* v, bool lo) {
    __nv_bfloat16 h[4];
#pragma unroll
    for (int j = 0; j < 4; j++) {
        __nv_bfloat16 hh = __float2bfloat16_rn(v[j]);
        h[j] = lo ? __float2bfloat16_rn(v[j] - __bfloat162float(hh)) : hh;
    }
    uint2 r;
    r.x = (uint32_t)__bfloat16_as_ushort(h[0]) |
          ((uint32_t)__bfloat16_as_ushort(h[1]) << 16);
    r.y = (uint32_t)__bfloat16_as_ushort(h[2]) |
          ((uint32_t)__bfloat16_as_ushort(h[3]) << 16);
    return r;
}

#define MMA_OP(d, A, b0, b1)                                                  \
    asm volatile("mma.sync.aligned.m16n8k16.row.col.f32.bf16.bf16.f32 "       \
                 "{%0,%1,%2,%3},{%4,%5,%6,%7},{%8,%9},{%0,%1,%2,%3};"         \
                 : "+f"(d[0]), "+f"(d[1]), "+f"(d[2]), "+f"(d[3])             \
                 : "r"(A[0]), "r"(A[1]), "r"(A[2]), "r"(A[3]),                \
                   "r"(b0), "r"(b1))

#define LDSM4(r, addr)                                                        \
    asm volatile("ldmatrix.sync.aligned.m8n8.x4.shared.b16 {%0,%1,%2,%3},[%4];"\
        : "=r"((r)[0]), "=r"((r)[1]), "=r"((r)[2]), "=r"((r)[3]) : "r"(addr))

// ---------------------------------------------------------------------------
// K1 fused: blocks [0,128): xs partials + xm partials + sb bf16 split.
//           blocks [128, 128+4096): Wqkv/Wout bf16 hi/lo split.
// ---------------------------------------------------------------------------
__global__ __launch_bounds__(256) void xs_split_kernel(
    const float* __restrict__ x, const float* __restrict__ sb,
    const float* __restrict__ Wqkv, const float* __restrict__ Wout)
{
    const int tid = threadIdx.x;
    if ((int)blockIdx.x >= 128) {
        int i = (blockIdx.x - 128) * 256 + tid;
        const int NQ4 = 3 * 1024 * 1024 / 4;
        const float* src;
        __nv_bfloat16 *hi, *lo;
        int j;
        if (i < NQ4) { src = Wqkv; hi = g_wqhi; lo = g_wqlo; j = i; }
        else { src = Wout; hi = g_wohi; lo = g_wolo; j = i - NQ4;
               if (j >= 1024 * 1024 / 4) return; }
        float4 v = ((const float4*)src)[j];
        float vv[4] = { v.x, v.y, v.z, v.w };
        ((uint2*)hi)[j] = pack_hilo4(vv, false);
        ((uint2*)lo)[j] = pack_hilo4(vv, true);
        return;
    }

    const int b = blockIdx.x >> 5, s = blockIdx.x & 31;
    const int d0 = tid * 4;
    const int t0 = s * 128;

    __shared__ __align__(16) float sbs[128][32];
    {
        int e = tid;
#pragma unroll
        for (int i = 0; i < 4; i++, e += 256) {
            int tt = e >> 3, k4 = (e & 7) * 4;
            size_t gofs = ((size_t)b * Tc + t0 + tt) * 32 + k4;
            float4 v = *(const float4*)(sb + gofs);
            *(float4*)&sbs[tt][k4] = v;
            float vv[4] = { v.x, v.y, v.z, v.w };
            ((uint2*)g_sbhi)[gofs / 4] = pack_hilo4(vv, false);
            ((uint2*)g_sblo)[gofs / 4] = pack_hilo4(vv, true);
        }
    }
    __syncthreads();

    float acc[32][4];
#pragma unroll
    for (int k = 0; k < 32; k++)
#pragma unroll
        for (int j = 0; j < 4; j++) acc[k][j] = 0.f;
    float am[4] = {0.f, 0.f, 0.f, 0.f};

    const float* xb = x + ((size_t)b * Tc + t0) * Dc + d0;
    for (int t = 0; t < 128; t++) {
        float4 xv = *(const float4*)(xb + (size_t)t * Dc);
        float v[4] = { xv.x, xv.y, xv.z, xv.w };
#pragma unroll
        for (int j = 0; j < 4; j++) am[j] += v[j];
#pragma unroll
        for (int k8 = 0; k8 < 8; k8++) {
            float4 sv = *(const float4*)&sbs[t][k8 * 4];
            float sk[4] = { sv.x, sv.y, sv.z, sv.w };
#pragma unroll
            for (int ki = 0; ki < 4; ki++)
#pragma unroll
                for (int j = 0; j < 4; j++)
                    acc[k8 * 4 + ki][j] = fmaf(sk[ki], v[j], acc[k8 * 4 + ki][j]);
        }
    }

    float* op = g_xs_p + (size_t)s * 131072 + (size_t)b * 32 * 1024 + d0;
#pragma unroll
    for (int k = 0; k < 32; k++)
        *(float4*)(op + k * 1024) = make_float4(acc[k][0], acc[k][1],
                                                acc[k][2], acc[k][3]);
    *(float4*)(g_xm_p + (size_t)s * 4096 + b * 1024 + d0) =
        make_float4(am[0], am[1], am[2], am[3]);
}

// ---------------------------------------------------------------------------
// Reduce xs partials -> bf16 hi/lo; xm partials -> fp32.
// ---------------------------------------------------------------------------
__global__ void reduce_xs_xm()
{
    int i = blockIdx.x * blockDim.x + threadIdx.x;
    if (i < 32768) {
        float4 a = make_float4(0.f, 0.f, 0.f, 0.f);
#pragma unroll 4
        for (int s = 0; s < NS1; s++) {
            float4 v = ((const float4*)g_xs_p)[(size_t)s * 32768 + i];
            a.x += v.x; a.y += v.y; a.z += v.z; a.w += v.w;
        }
        float vv[4] = { a.x, a.y, a.z, a.w };
        ((uint2*)g_xshi)[i] = pack_hilo4(vv, false);
        ((uint2*)g_xslo)[i] = pack_hilo4(vv, true);
    } else if (i < 32768 + 1024) {
        int j = i - 32768;
        float4 a = make_float4(0.f, 0.f, 0.f, 0.f);
#pragma unroll 4
        for (int s = 0; s < NS1; s++) {
            float4 v = ((const float4*)g_xm_p)[(size_t)s * 1024 + j];
            a.x += v.x; a.y += v.y; a.z += v.z; a.w += v.w;
        }
        ((float4*)g_xm)[j] = a;
    }
}

// ---------------------------------------------------------------------------
// HMMA GEMM NT, M=128, split-K, 3-product bf16 split + fused qm GEMV blocks.
// ---------------------------------------------------------------------------
#define KT      32
#define RB      80
#define TILE_B  (128 * RB)
#define STAGE_B (4 * TILE_B)

__global__ void __launch_bounds__(256, 2) gemm_mma_sk(
    const __nv_bfloat16* __restrict__ Ahi, const __nv_bfloat16* __restrict__ Alo,
    const __nv_bfloat16* __restrict__ Bhi, const __nv_bfloat16* __restrict__ Blo,
    float* __restrict__ Cp, int N, int kPerSplit, int nGemm,
    const float* __restrict__ WqF)
{
    const int tid = threadIdx.x;
    if ((int)blockIdx.x >= nGemm) {
        const int w = (blockIdx.x - nGemm) * 8 + (tid >> 5);
        const int lane = tid & 31;
        const int b = w >> 10, o = w & 1023;
        const float4* xm = (const float4*)(g_xm + b * 1024);
        const float4* wr = (const float4*)(WqF + (size_t)o * 1024);
        float s = 0.f;
#pragma unroll
        for (int j = 0; j < 8; j++) {
            float4 a = xm[lane + j * 32];
            float4 c = wr[lane + j * 32];
            s = fmaf(a.x, c.x, s); s = fmaf(a.y, c.y, s);
            s = fmaf(a.z, c.z, s); s = fmaf(a.w, c.w, s);
        }
#pragma unroll
        for (int off = 16; off; off >>= 1)
            s += __shfl_down_sync(0xffffffffu, s, off);
        if (lane == 0) g_qm[b * 1024 + o] = s;
        return;
    }

    extern __shared__ char smem[];
    const int Kd = 1024;
    const uint32_t sbase = smem_u32(smem);
    const int wid = tid >> 5, lane = tid & 31;
    const int nCols = N >> 7;
    const int col0 = (blockIdx.x % nCols) * 128;
    const int kb = (blockIdx.x / nCols) * kPerSplit;
    const int wm = wid >> 2, wn = wid & 3;

    const __nv_bfloat16* s0 = Ahi + kb;
    const __nv_bfloat16* s1 = Alo + kb;
    const __nv_bfloat16* s2 = Bhi + (size_t)col0 * Kd + kb;
    const __nv_bfloat16* s3 = Blo + (size_t)col0 * Kd + kb;

    const int r0c = tid >> 2, c0c = tid & 3;
    const int r1c = (tid + 256) >> 2, c1c = (tid + 256) & 3;

#define LOAD_STAGE(kt, buf)                                                   \
    do {                                                                      \
        uint32_t db = sbase + (buf) * STAGE_B;                                \
        const __nv_bfloat16* srcs[4] = { s0, s1, s2, s3 };                    \
        _Pragma("unroll")                                                     \
        for (int a = 0; a < 4; a++) {                                         \
            const char* g0 = (const char*)(srcs[a] + (size_t)r0c * Kd + (kt) * KT) + c0c * 16; \
            const char* g1 = (const char*)(srcs[a] + (size_t)r1c * Kd + (kt) * KT) + c1c * 16; \
            uint32_t p0 = db + a * TILE_B + r0c * RB + c0c * 16;              \
            uint32_t p1 = db + a * TILE_B + r1c * RB + c1c * 16;              \
            asm volatile("cp.async.cg.shared.global [%0],[%1],16;" :: "r"(p0), "l"(g0)); \
            asm volatile("cp.async.cg.shared.global [%0],[%1],16;" :: "r"(p1), "l"(g1)); \
        }                                                                     \
        asm volatile("cp.async.commit_group;");                               \
    } while (0)

    float acc[4][4][4];
#pragma unroll
    for (int i = 0; i < 4; i++)
#pragma unroll
        for (int j = 0; j < 4; j++)
#pragma unroll
            for (int q = 0; q < 4; q++) acc[i][j][q] = 0.f;

    LOAD_STAGE(0, 0);
    int buf = 0;
    const int nTiles = kPerSplit / KT;

    for (int kt = 0; kt < nTiles; kt++) {
        asm volatile("cp.async.wait_group 0;");
        __syncthreads();
        if (kt + 1 < nTiles) LOAD_STAGE(kt + 1, buf ^ 1);

        const uint32_t db = sbase + buf * STAGE_B;
#pragma unroll
        for (int ks = 0; ks < 2; ks++) {
            uint32_t rah[4][4], ral[4][4];
#pragma unroll
            for (int mf = 0; mf < 4; mf++) {
                int r = wm * 64 + mf * 16 + (lane & 15);
                uint32_t ad = db + r * RB + ks * 32 + ((lane >> 4) & 1) * 16;
                LDSM4(rah[mf], ad);
                LDSM4(ral[mf], ad + TILE_B);
            }
            uint32_t rbh[2][4], rbl[2][4];
#pragma unroll
            for (int np = 0; np < 2; np++) {
                int r = wn * 32 + (np * 2 + (lane >> 4)) * 8 + (lane & 7);
                uint32_t bd = db + 2 * TILE_B + r * RB + ks * 32 + ((lane >> 3) & 1) * 16;
                LDSM4(rbh[np], bd);
                LDSM4(rbl[np], bd + TILE_B);
            }
#pragma unroll
            for (int mf = 0; mf < 4; mf++)
#pragma unroll
                for (int nf = 0; nf < 4; nf++)
                    MMA_OP(acc[mf][nf], rah[mf], rbh[nf >> 1][(nf & 1) * 2],
                           rbh[nf >> 1][(nf & 1) * 2 + 1]);
#pragma unroll
            for (int mf = 0; mf < 4; mf++)
#pragma unroll
                for (int nf = 0; nf < 4; nf++)
                    MMA_OP(acc[mf][nf], rah[mf], rbl[nf >> 1][(nf & 1) * 2],
                           rbl[nf >> 1][(nf & 1) * 2 + 1]);
#pragma unroll
            for (int mf = 0; mf < 4; mf++)
#pragma unroll
                for (int nf = 0; nf < 4; nf++)
                    MMA_OP(acc[mf][nf], ral[mf], rbh[nf >> 1][(nf & 1) * 2],
                           rbh[nf >> 1][(nf & 1) * 2 + 1]);
        }
        __syncthreads();
        buf ^= 1;
    }

    float* C = Cp + (size_t)(blockIdx.x / nCols) * 128 * N;
    const int mrow = lane >> 2, ncol = (lane & 3) * 2;
#pragma unroll
    for (int mf = 0; mf < 4; mf++) {
#pragma unroll
        for (int nf = 0; nf < 4; nf++) {
            int r  = wm * 64 + mf * 16 + mrow;
            int cc = col0 + wn * 32 + nf * 8 + ncol;
            *(float2*)(C + (size_t)r * N + cc) =
                make_float2(acc[mf][nf][0], acc[mf][nf][1]);
            *(float2*)(C + (size_t)(r + 8) * N + cc) =
                make_float2(acc[mf][nf][2], acc[mf][nf][3]);
        }
    }
#undef LOAD_STAGE
}

// ---------------------------------------------------------------------------
// Z GEMM (no split-K): Z[m][d] = sum_k ws2[m][k]*Wout[d][k], grid 8 col-tiles.
// Epilogue writes Zt[b][d][k] bf16 hi/lo directly (no reduce kernel).
// ---------------------------------------------------------------------------
__global__ void __launch_bounds__(256, 2) gemm_Z_kernel()
{
    extern __shared__ char smem[];
    const int Kd = 1024;
    const int tid = threadIdx.x;
    const uint32_t sbase = smem_u32(smem);
    const int wid = tid >> 5, lane = tid & 31;
    const int col0 = blockIdx.x * 128;
    const int wm = wid >> 2, wn = wid & 3;

    const __nv_bfloat16* s0 = g_wshi;
    const __nv_bfloat16* s1 = g_wslo;
    const __nv_bfloat16* s2 = g_wohi + (size_t)col0 * Kd;
    const __nv_bfloat16* s3 = g_wolo + (size_t)col0 * Kd;

    const int r0c = tid >> 2, c0c = tid & 3;
    const int r1c = (tid + 256) >> 2, c1c = (tid + 256) & 3;

#define LOAD_STAGEZ(kt, buf)                                                  \
    do {                                                                      \
        uint32_t db = sbase + (buf) * STAGE_B;                                \
        const __nv_bfloat16* srcs[4] = { s0, s1, s2, s3 };                    \
        _Pragma("unroll")                                                     \
        for (int a = 0; a < 4; a++) {                                         \
            const char* g0 = (const char*)(srcs[a] + (size_t)r0c * Kd + (kt) * KT) + c0c * 16; \
            const char* g1 = (const char*)(srcs[a] + (size_t)r1c * Kd + (kt) * KT) + c1c * 16; \
            uint32_t p0 = db + a * TILE_B + r0c * RB + c0c * 16;              \
            uint32_t p1 = db + a * TILE_B + r1c * RB + c1c * 16;              \
            asm volatile("cp.async.cg.shared.global [%0],[%1],16;" :: "r"(p0), "l"(g0)); \
            asm volatile("cp.async.cg.shared.global [%0],[%1],16;" :: "r"(p1), "l"(g1)); \
        }                                                                     \
        asm volatile("cp.async.commit_group;");                               \
    } while (0)

    float acc[4][4][4];
#pragma unroll
    for (int i = 0; i < 4; i++)
#pragma unroll
        for (int j = 0; j < 4; j++)
#pragma unroll
            for (int q = 0; q < 4; q++) acc[i][j][q] = 0.f;

    LOAD_STAGEZ(0, 0);
    int buf = 0;
    const int nTiles = Kd / KT;          // 32

    for (int kt = 0; kt < nTiles; kt++) {
        asm volatile("cp.async.wait_group 0;");
        __syncthreads();
        if (kt + 1 < nTiles) LOAD_STAGEZ(kt + 1, buf ^ 1);

        const uint32_t db = sbase + buf * STAGE_B;
#pragma unroll
        for (int ks = 0; ks < 2; ks++) {
            uint32_t rah[4][4], ral[4][4];
#pragma unroll
            for (int mf = 0; mf < 4; mf++) {
                int r = wm * 64 + mf * 16 + (lane & 15);
                uint32_t ad = db + r * RB + ks * 32 + ((lane >> 4) & 1) * 16;
                LDSM4(rah[mf], ad);
                LDSM4(ral[mf], ad + TILE_B);
            }
            uint32_t rbh[2][4], rbl[2][4];
#pragma unroll
            for (int np = 0; np < 2; np++) {
                int r = wn * 32 + (np * 2 + (lane >> 4)) * 8 + (lane & 7);
                uint32_t bd = db + 2 * TILE_B + r * RB + ks * 32 + ((lane >> 3) & 1) * 16;
                LDSM4(rbh[np], bd);
                LDSM4(rbl[np], bd + TILE_B);
            }
#pragma unroll
            for (int mf = 0; mf < 4; mf++)
#pragma unroll
                for (int nf = 0; nf < 4; nf++)
                    MMA_OP(acc[mf][nf], rah[mf], rbh[nf >> 1][(nf & 1) * 2],
                           rbh[nf >> 1][(nf & 1) * 2 + 1]);
#pragma unroll
            for (int mf = 0; mf < 4; mf++)
#pragma unroll
                for (int nf = 0; nf < 4; nf++)
                    MMA_OP(acc[mf][nf], rah[mf], rbl[nf >> 1][(nf & 1) * 2],
                           rbl[nf >> 1][(nf & 1) * 2 + 1]);
#pragma unroll
            for (int mf = 0; mf < 4; mf++)
#pragma unroll
                for (int nf = 0; nf < 4; nf++)
                    MMA_OP(acc[mf][nf], ral[mf], rbh[nf >> 1][(nf & 1) * 2],
                           rbh[nf >> 1][(nf & 1) * 2 + 1]);
        }
        __syncthreads();
        buf ^= 1;
    }

    // epilogue: write Zt[b][d][k] bf16 hi/lo (transposed scatter)
    const int mrow = lane >> 2, ncol = (lane & 3) * 2;
#pragma unroll
    for (int mf = 0; mf < 4; mf++) {
#pragma unroll
        for (int nf = 0; nf < 4; nf++) {
#pragma unroll
            for (int q = 0; q < 4; q++) {
                int r = wm * 64 + mf * 16 + mrow + (q >> 1) * 8;
                int d = col0 + wn * 32 + nf * 8 + ncol + (q & 1);
                int b = r >> 5, k = r & 31;
                float v = acc[mf][nf][q];
                __nv_bfloat16 hh = __float2bfloat16_rn(v);
                size_t oi = ((size_t)b * 1024 + d) * 32 + k;
                g_Zthi[oi] = hh;
                g_Ztlo[oi] = __float2bfloat16_rn(v - __bfloat162float(hh));
            }
        }
    }
#undef LOAD_STAGEZ
}

// ---------------------------------------------------------------------------
// Fused (512 threads): blocks 0..127: reduce spec partials + 16 ODEs +
// ws2 bf16 split. Blocks 128..191: pulse MLP.
// ---------------------------------------------------------------------------
__global__ __launch_bounds__(512) void soliton_pulse_kernel(
    const float* __restrict__ d_a, const float* __restrict__ d_b,
    const float* __restrict__ filt,
    const float* __restrict__ W1, const float* __restrict__ b1,
    const float* __restrict__ W2, const float* __restrict__ b2,
    float* __restrict__ out_resp, float* __restrict__ out_pulse)
{
    const int tid = threadIdx.x;
    if (blockIdx.x < 128) {
        const int m = blockIdx.x;
        const int b = m >> 5, k = m & 31;
        __shared__ __align__(16) float srow[3072];
        __shared__ float resp_s[16];

        const size_t SPL4 = 128 * 3072 / 4;
        const size_t rb4 = (size_t)m * 768;
        for (int idx = tid; idx < 768; idx += 512) {
            float4 a = make_float4(0.f, 0.f, 0.f, 0.f);
#pragma unroll
            for (int s = 0; s < SKS; s++) {
                float4 v = ((const float4*)g_spec_p)[s * SPL4 + rb4 + idx];
                a.x += v.x; a.y += v.y; a.z += v.z; a.w += v.w;
            }
            ((float4*)srow)[idx] = a;
        }
        __syncthreads();

        if (tid < 16) {
            const int h = tid;
            float dot = 0.f;
#pragma unroll
            for (int d = 0; d < 64; d++)
                dot = fmaf(srow[h * 64 + d], srow[1024 + h * 64 + d], dot);

            float f = 1.f / (1.f + expf(-filt[h * 32 + k]));
            float stim = dot * 0.125f * f;

            const float a = d_a[0], bb = d_b[0];
            float scale = fmaxf(fabsf(stim), 1e-6f);
            float sn = stim / scale;
            float I = (fabsf(stim) > 0.5f) ? sn : sn * 0.1f;
            float v = 0.f, w = 0.f;
            const float dt = 0.2f;
#pragma unroll
            for (int s = 0; s < 5; s++) {
                float dv = v - v * v * v * (1.f / 3.f) - w + I;
                float dw = (v + a - bb * w) * 10.f;
                v = fminf(fmaxf(v + dt * dv, -3.f), 3.f);
                w = fminf(fmaxf(w + dt * dw, -3.f), 3.f);
            }
            float resp = v * scale;
            resp_s[h] = resp;
            out_resp[b * 512 + h * 32 + k] = resp;
        }
        __syncthreads();

        if (tid < 256) {
            const int h = tid >> 4;
            float r = resp_s[h];
            float4 vv = ((const float4*)srow)[512 + tid];
            float wv[4] = { r * vv.x, r * vv.y, r * vv.z, r * vv.w };
            ((uint2*)g_wshi)[(size_t)m * 256 + tid] = pack_hilo4(wv, false);
            ((uint2*)g_wslo)[(size_t)m * 256 + tid] = pack_hilo4(wv, true);
        }
    } else {
        const int bh = blockIdx.x - 128;
        const int b = bh >> 4, h = bh & 15;
        if (tid >= 32) return;
        const float* qm = g_qm + b * 1024 + h * 64;
        float acc = b1[tid];
#pragma unroll
        for (int dd = 0; dd < 64; dd++)
            acc = fmaf(qm[dd] * (1.0f / Tc), W1[tid * 64 + dd], acc);
        float h1 = acc / (1.f + expf(-acc));
        float pp = h1 * W2[tid];
#pragma unroll
        for (int off = 16; off; off >>= 1)
            pp += __shfl_down_sync(0xffffffffu, pp, off);
        if (tid == 0) {
            float xv = pp + b2[0];
            float sp = (xv > 20.f) ? xv : log1pf(expf(xv));
            out_pulse[bh] = 4.0f + sp;
        }
    }
}

// ---------------------------------------------------------------------------
// out HMMA: out[b, t0:t0+128, d0:d0+128] = sb[b,t,:] @ Zt[b,d,:]^T  (K=32)
// ---------------------------------------------------------------------------
__global__ __launch_bounds__(256, 2) void out_mma_kernel(float* __restrict__ out)
{
    __shared__ __align__(16) char smem[4 * TILE_B];
    const int tid = threadIdx.x, wid = tid >> 5, lane = tid & 31;
    const int t0 = blockIdx.x * 128, d0 = blockIdx.y * 128, b = blockIdx.z;
    const int wm = wid >> 2, wn = wid & 3;
    const uint32_t sbase = smem_u32(smem);

    {
        const char* srcs[4] = {
            (const char*)(g_sbhi + ((size_t)b * Tc + t0) * 32),
            (const char*)(g_sblo + ((size_t)b * Tc + t0) * 32),
            (const char*)(g_Zthi + ((size_t)b * 1024 + d0) * 32),
            (const char*)(g_Ztlo + ((size_t)b * 1024 + d0) * 32) };
#pragma unroll
        for (int a = 0; a < 4; a++) {
#pragma unroll
            for (int i = 0; i < 2; i++) {
                int e = tid + i * 256;
                int r = e >> 2, c = e & 3;
                uint4 v = *(const uint4*)(srcs[a] + (size_t)r * 64 + c * 16);
                *(uint4*)(smem + a * TILE_B + r * RB + c * 16) = v;
            }
        }
    }
    __syncthreads();

    float acc[4][4][4];
#pragma unroll
    for (int i = 0; i < 4; i++)
#pragma unroll
        for (int j = 0; j < 4; j++)
#pragma unroll
            for (int q = 0; q < 4; q++) acc[i][j][q] = 0.f;

#pragma unroll
    for (int ks = 0; ks < 2; ks++) {
        uint32_t rah[4][4], ral[4][4];
#pragma unroll
        for (int mf = 0; mf < 4; mf++) {
            int r = wm * 64 + mf * 16 + (lane & 15);
            uint32_t ad = sbase + r * RB + ks * 32 + ((lane >> 4) & 1) * 16;
            LDSM4(rah[mf], ad);
            LDSM4(ral[mf], ad + TILE_B);
        }
        uint32_t rbh[2][4], rbl[2][4];
#pragma unroll
        for (int np = 0; np < 2; np++) {
            int r = wn * 32 + (np * 2 + (lane >> 4)) * 8 + (lane & 7);
            uint32_t bd = sbase + 2 * TILE_B + r * RB + ks * 32 + ((lane >> 3) & 1) * 16;
            LDSM4(rbh[np], bd);
            LDSM4(rbl[np], bd + TILE_B);
        }
#pragma unroll
        for (int mf = 0; mf < 4; mf++)
#pragma unroll
            for (int nf = 0; nf < 4; nf++)
                MMA_OP(acc[mf][nf], rah[mf], rbh[nf >> 1][(nf & 1) * 2],
                       rbh[nf >> 1][(nf & 1) * 2 + 1]);
#pragma unroll
        for (int mf = 0; mf < 4; mf++)
#pragma unroll
            for (int nf = 0; nf < 4; nf++)
                MMA_OP(acc[mf][nf], rah[mf], rbl[nf >> 1][(nf & 1) * 2],
                       rbl[nf >> 1][(nf & 1) * 2 + 1]);
#pragma unroll
        for (int mf = 0; mf < 4; mf++)
#pragma unroll
            for (int nf = 0; nf < 4; nf++)
                MMA_OP(acc[mf][nf], ral[mf], rbh[nf >> 1][(nf & 1) * 2],
                       rbh[nf >> 1][(nf & 1) * 2 + 1]);
    }

    const int mrow = lane >> 2, ncol = (lane & 3) * 2;
#pragma unroll
    for (int mf = 0; mf < 4; mf++) {
#pragma unroll
        for (int nf = 0; nf < 4; nf++) {
            int r  = t0 + wm * 64 + mf * 16 + mrow;
            int cc = d0 + wn * 32 + nf * 8 + ncol;
            *(float2*)(out + ((size_t)b * Tc + r) * Dc + cc) =
                make_float2(acc[mf][nf][0], acc[mf][nf][1]);
            *(float2*)(out + ((size_t)b * Tc + r + 8) * Dc + cc) =
                make_float2(acc[mf][nf][2], acc[mf][nf][3]);
        }
    }
}

// ---------------------------------------------------------------------------
// Launch
// ---------------------------------------------------------------------------
extern "C" void kernel_launch(void* const* d_in, const int* in_sizes, int n_in,
                              void* d_out, int out_size)
{
    const float* x    = (const float*)d_in[0];
    const float* sb   = (const float*)d_in[1];
    const float* Wqkv = (const float*)d_in[2];
    const float* Wout = (const float*)d_in[3];
    const float* a    = (const float*)d_in[4];
    const float* b    = (const float*)d_in[5];
    const float* W1   = (const float*)d_in[6];
    const float* b1   = (const float*)d_in[7];
    const float* W2   = (const float*)d_in[8];
    const float* b2   = (const float*)d_in[9];
    const float* filt = (const float*)d_in[10];

    float* out       = (float*)d_out;
    float* out_pulse = out + (size_t)Bc * Tc * Dc;
    float* out_resp  = out_pulse + Bc * Hc;

    float* pspec_p;
    cudaGetSymbolAddress((void**)&pspec_p, g_spec_p);
    __nv_bfloat16 *pxshi, *pxslo, *pwqhi, *pwqlo;
    cudaGetSymbolAddress((void**)&pxshi, g_xshi);
    cudaGetSymbolAddress((void**)&pxslo, g_xslo);
    cudaGetSymbolAddress((void**)&pwqhi, g_wqhi);
    cudaGetSymbolAddress((void**)&pwqlo, g_wqlo);

    const int GEMM_SMEM = 2 * STAGE_B;
    cudaFuncSetAttribute(gemm_mma_sk, cudaFuncAttributeMaxDynamicSharedMemorySize,
                         GEMM_SMEM);
    cudaFuncSetAttribute(gemm_Z_kernel, cudaFuncAttributeMaxDynamicSharedMemorySize,
                         GEMM_SMEM);

    // 1) xs partials + sb split + weight split (fused)
    xs_split_kernel<<<128 + 4096, 256>>>(x, sb, Wqkv, Wout);

    // 2) reduce -> xs bf16 hi/lo, xm fp32
    reduce_xs_xm<<<(32768 + 1024 + 255) / 256, 256>>>();

    // 3) spec partials [HMMA split-K 8] ++ qm GEMV fused
    gemm_mma_sk<<<24 * SKS + 512, 256, GEMM_SMEM>>>(
        pxshi, pxslo, pwqhi, pwqlo, pspec_p, 3072, 1024 / SKS, 24 * SKS, Wqkv);

    // 4) spec reduce + soliton + ws2 split + pulse MLP
    soliton_pulse_kernel<<<128 + 64, 512>>>(a, b, filt, W1, b1, W2, b2,
                                            out_resp, out_pulse);

    // 5) Z = ws2 @ Wout^T [HMMA, full K, direct Zt epilogue]
    gemm_Z_kernel<<<8, 256, GEMM_SMEM>>>();

    // 6) out = sb @ Zt^T [HMMA, K=32]
    out_mma_kernel<<<dim3(Tc / 128, Dc / 128, Bc), 256>>>(out);
}

// round 15
// speedup vs baseline: 1.6161x; 1.4115x over previous
#include <cuda_runtime.h>
#include <cuda_bf16.h>
#include <math.h>
#include <stdint.h>

// Problem constants
#define Bc  4
#define Tc  4096
#define Dc  1024
#define Hc  16
#define HDc 64
#define Kc  32

#define NS1 32      // t-slices for xs build (128 t each)
#define SKS 8       // split-K for spec GEMM (slab 128)
#define SKZ 16      // split-K for Z GEMM   (slab 64)

// ---------------- scratch (static device arrays) ----------------
__device__ float g_xs_p[NS1 * 128 * 1024];       // xs partials
__device__ float g_xm_p[NS1 * Bc * 1024];        // xmean partials
__device__ float g_xm[Bc * 1024];                // sum_t x
__device__ float g_qm[Bc * 1024];                // xm @ Wq^T (unnormalized)
__device__ float g_spec_p[SKS * 128 * 3072];     // spec GEMM partials
__device__ float g_Zp[SKZ * 128 * 1024];         // Z GEMM partials
__device__ __nv_bfloat16 g_xshi[128 * 1024], g_xslo[128 * 1024];
__device__ __nv_bfloat16 g_wqhi[3 * 1024 * 1024], g_wqlo[3 * 1024 * 1024];
__device__ __nv_bfloat16 g_wohi[1024 * 1024], g_wolo[1024 * 1024];
__device__ __nv_bfloat16 g_wshi[128 * 1024], g_wslo[128 * 1024];
__device__ __nv_bfloat16 g_sbhi[Bc * Tc * 32], g_sblo[Bc * Tc * 32];
__device__ __nv_bfloat16 g_Zthi[Bc * 1024 * 32], g_Ztlo[Bc * 1024 * 32];

__device__ __forceinline__ uint32_t smem_u32(const void* p) {
    uint32_t a;
    asm("{ .reg .u64 t; cvta.to.shared.u64 t, %1; cvt.u32.u64 %0, t; }"
        : "=r"(a) : "l"(p));
    return a;
}
__device__ __forceinline__ uint2 pack_hilo4(const float* v, bool lo) {
    __nv_bfloat16 h[4];
#pragma unroll
    for (int j = 0; j < 4; j++) {
        __nv_bfloat16 hh = __float2bfloat16_rn(v[j]);
        h[j] = lo ? __float2bfloat16_rn(v[j] - __bfloat162float(hh)) : hh;
    }
    uint2 r;
    r.x = (uint32_t)__bfloat16_as_ushort(h[0]) |
          ((uint32_t)__bfloat16_as_ushort(h[1]) << 16);
    r.y = (uint32_t)__bfloat16_as_ushort(h[2]) |
          ((uint32_t)__bfloat16_as_ushort(h[3]) << 16);
    return r;
}

#define MMA_OP(d, A, b0, b1)                                                  \
    asm volatile("mma.sync.aligned.m16n8k16.row.col.f32.bf16.bf16.f32 "       \
                 "{%0,%1,%2,%3},{%4,%5,%6,%7},{%8,%9},{%0,%1,%2,%3};"         \
                 : "+f"(d[0]), "+f"(d[1]), "+f"(d[2]), "+f"(d[3])             \
                 : "r"(A[0]), "r"(A[1]), "r"(A[2]), "r"(A[3]),                \
                   "r"(b0), "r"(b1))

#define LDSM4(r, addr)                                                        \
    asm volatile("ldmatrix.sync.aligned.m8n8.x4.shared.b16 {%0,%1,%2,%3},[%4];"\
        : "=r"((r)[0]), "=r"((r)[1]), "=r"((r)[2]), "=r"((r)[3]) : "r"(addr))

// ---------------------------------------------------------------------------
// K1 fused: blocks [0,256): xs partials + xm partials + sb bf16 split.
//   decode: b = bid>>6, s = (bid>>1)&31, dh = bid&1; thread owns 2 d's.
//   acc[32][2] -> ~80 regs -> 2 CTAs/SM resident (vs 1 before).
// Blocks [256, 256+4096): Wqkv/Wout bf16 hi/lo split.
// ---------------------------------------------------------------------------
__global__ __launch_bounds__(256, 2) void xs_split_kernel(
    const float* __restrict__ x, const float* __restrict__ sb,
    const float* __restrict__ Wqkv, const float* __restrict__ Wout)
{
    const int tid = threadIdx.x;
    if ((int)blockIdx.x >= 256) {
        int i = (blockIdx.x - 256) * 256 + tid;
        const int NQ4 = 3 * 1024 * 1024 / 4;
        const float* src;
        __nv_bfloat16 *hi, *lo;
        int j;
        if (i < NQ4) { src = Wqkv; hi = g_wqhi; lo = g_wqlo; j = i; }
        else { src = Wout; hi = g_wohi; lo = g_wolo; j = i - NQ4;
               if (j >= 1024 * 1024 / 4) return; }
        float4 v = ((const float4*)src)[j];
        float vv[4] = { v.x, v.y, v.z, v.w };
        ((uint2*)hi)[j] = pack_hilo4(vv, false);
        ((uint2*)lo)[j] = pack_hilo4(vv, true);
        return;
    }

    const int b = blockIdx.x >> 6;
    const int s = (blockIdx.x >> 1) & 31;
    const int dh = blockIdx.x & 1;
    const int d0 = dh * 512 + tid * 2;
    const int t0 = s * 128;

    __shared__ __align__(16) float sbs[128][32];
    {
        int e = tid;
#pragma unroll
        for (int i = 0; i < 4; i++, e += 256) {
            int tt = e >> 3, k4 = (e & 7) * 4;
            size_t gofs = ((size_t)b * Tc + t0 + tt) * 32 + k4;
            float4 v = *(const float4*)(sb + gofs);
            *(float4*)&sbs[tt][k4] = v;
            if (dh == 0) {
                float vv[4] = { v.x, v.y, v.z, v.w };
                ((uint2*)g_sbhi)[gofs / 4] = pack_hilo4(vv, false);
                ((uint2*)g_sblo)[gofs / 4] = pack_hilo4(vv, true);
            }
        }
    }
    __syncthreads();

    float acc[32][2];
#pragma unroll
    for (int k = 0; k < 32; k++) { acc[k][0] = 0.f; acc[k][1] = 0.f; }
    float am0 = 0.f, am1 = 0.f;

    const float* xb = x + ((size_t)b * Tc + t0) * Dc + d0;
    for (int t = 0; t < 128; t++) {
        float2 xv = *(const float2*)(xb + (size_t)t * Dc);
        am0 += xv.x; am1 += xv.y;
#pragma unroll
        for (int k8 = 0; k8 < 8; k8++) {
            float4 sv = *(const float4*)&sbs[t][k8 * 4];
            float sk[4] = { sv.x, sv.y, sv.z, sv.w };
#pragma unroll
            for (int ki = 0; ki < 4; ki++) {
                acc[k8 * 4 + ki][0] = fmaf(sk[ki], xv.x, acc[k8 * 4 + ki][0]);
                acc[k8 * 4 + ki][1] = fmaf(sk[ki], xv.y, acc[k8 * 4 + ki][1]);
            }
        }
    }

    float* op = g_xs_p + (size_t)s * 131072 + (size_t)b * 32 * 1024 + d0;
#pragma unroll
    for (int k = 0; k < 32; k++)
        *(float2*)(op + k * 1024) = make_float2(acc[k][0], acc[k][1]);
    *(float2*)(g_xm_p + (size_t)s * 4096 + b * 1024 + d0) =
        make_float2(am0, am1);
}

// ---------------------------------------------------------------------------
// Reduce xs partials -> bf16 hi/lo; xm partials -> fp32.
// ---------------------------------------------------------------------------
__global__ void reduce_xs_xm()
{
    int i = blockIdx.x * blockDim.x + threadIdx.x;
    if (i < 32768) {
        float4 a = make_float4(0.f, 0.f, 0.f, 0.f);
#pragma unroll 4
        for (int s = 0; s < NS1; s++) {
            float4 v = ((const float4*)g_xs_p)[(size_t)s * 32768 + i];
            a.x += v.x; a.y += v.y; a.z += v.z; a.w += v.w;
        }
        float vv[4] = { a.x, a.y, a.z, a.w };
        ((uint2*)g_xshi)[i] = pack_hilo4(vv, false);
        ((uint2*)g_xslo)[i] = pack_hilo4(vv, true);
    } else if (i < 32768 + 1024) {
        int j = i - 32768;
        float4 a = make_float4(0.f, 0.f, 0.f, 0.f);
#pragma unroll 4
        for (int s = 0; s < NS1; s++) {
            float4 v = ((const float4*)g_xm_p)[(size_t)s * 1024 + j];
            a.x += v.x; a.y += v.y; a.z += v.z; a.w += v.w;
        }
        ((float4*)g_xm)[j] = a;
    }
}

// ---------------------------------------------------------------------------
// HMMA GEMM NT, M=128, split-K, 3-product bf16 split + fused qm GEMV blocks.
// ---------------------------------------------------------------------------
#define KT      32
#define RB      80
#define TILE_B  (128 * RB)
#define STAGE_B (4 * TILE_B)

__global__ void __launch_bounds__(256, 2) gemm_mma_sk(
    const __nv_bfloat16* __restrict__ Ahi, const __nv_bfloat16* __restrict__ Alo,
    const __nv_bfloat16* __restrict__ Bhi, const __nv_bfloat16* __restrict__ Blo,
    float* __restrict__ Cp, int N, int kPerSplit, int nGemm,
    const float* __restrict__ WqF)
{
    const int tid = threadIdx.x;
    if ((int)blockIdx.x >= nGemm) {
        const int w = (blockIdx.x - nGemm) * 8 + (tid >> 5);
        const int lane = tid & 31;
        const int b = w >> 10, o = w & 1023;
        const float4* xm = (const float4*)(g_xm + b * 1024);
        const float4* wr = (const float4*)(WqF + (size_t)o * 1024);
        float s = 0.f;
#pragma unroll
        for (int j = 0; j < 8; j++) {
            float4 a = xm[lane + j * 32];
            float4 c = wr[lane + j * 32];
            s = fmaf(a.x, c.x, s); s = fmaf(a.y, c.y, s);
            s = fmaf(a.z, c.z, s); s = fmaf(a.w, c.w, s);
        }
#pragma unroll
        for (int off = 16; off; off >>= 1)
            s += __shfl_down_sync(0xffffffffu, s, off);
        if (lane == 0) g_qm[b * 1024 + o] = s;
        return;
    }

    extern __shared__ char smem[];
    const int Kd = 1024;
    const uint32_t sbase = smem_u32(smem);
    const int wid = tid >> 5, lane = tid & 31;
    const int nCols = N >> 7;
    const int col0 = (blockIdx.x % nCols) * 128;
    const int kb = (blockIdx.x / nCols) * kPerSplit;
    const int wm = wid >> 2, wn = wid & 3;

    const __nv_bfloat16* s0 = Ahi + kb;
    const __nv_bfloat16* s1 = Alo + kb;
    const __nv_bfloat16* s2 = Bhi + (size_t)col0 * Kd + kb;
    const __nv_bfloat16* s3 = Blo + (size_t)col0 * Kd + kb;

    const int r0c = tid >> 2, c0c = tid & 3;
    const int r1c = (tid + 256) >> 2, c1c = (tid + 256) & 3;

#define LOAD_STAGE(kt, buf)                                                   \
    do {                                                                      \
        uint32_t db = sbase + (buf) * STAGE_B;                                \
        const __nv_bfloat16* srcs[4] = { s0, s1, s2, s3 };                    \
        _Pragma("unroll")                                                     \
        for (int a = 0; a < 4; a++) {                                         \
            const char* g0 = (const char*)(srcs[a] + (size_t)r0c * Kd + (kt) * KT) + c0c * 16; \
            const char* g1 = (const char*)(srcs[a] + (size_t)r1c * Kd + (kt) * KT) + c1c * 16; \
            uint32_t p0 = db + a * TILE_B + r0c * RB + c0c * 16;              \
            uint32_t p1 = db + a * TILE_B + r1c * RB + c1c * 16;              \
            asm volatile("cp.async.cg.shared.global [%0],[%1],16;" :: "r"(p0), "l"(g0)); \
            asm volatile("cp.async.cg.shared.global [%0],[%1],16;" :: "r"(p1), "l"(g1)); \
        }                                                                     \
        asm volatile("cp.async.commit_group;");                               \
    } while (0)

    float acc[4][4][4];
#pragma unroll
    for (int i = 0; i < 4; i++)
#pragma unroll
        for (int j = 0; j < 4; j++)
#pragma unroll
            for (int q = 0; q < 4; q++) acc[i][j][q] = 0.f;

    LOAD_STAGE(0, 0);
    int buf = 0;
    const int nTiles = kPerSplit / KT;

    for (int kt = 0; kt < nTiles; kt++) {
        asm volatile("cp.async.wait_group 0;");
        __syncthreads();
        if (kt + 1 < nTiles) LOAD_STAGE(kt + 1, buf ^ 1);

        const uint32_t db = sbase + buf * STAGE_B;
#pragma unroll
        for (int ks = 0; ks < 2; ks++) {
            uint32_t rah[4][4], ral[4][4];
#pragma unroll
            for (int mf = 0; mf < 4; mf++) {
                int r = wm * 64 + mf * 16 + (lane & 15);
                uint32_t ad = db + r * RB + ks * 32 + ((lane >> 4) & 1) * 16;
                LDSM4(rah[mf], ad);
                LDSM4(ral[mf], ad + TILE_B);
            }
            uint32_t rbh[2][4], rbl[2][4];
#pragma unroll
            for (int np = 0; np < 2; np++) {
                int r = wn * 32 + (np * 2 + (lane >> 4)) * 8 + (lane & 7);
                uint32_t bd = db + 2 * TILE_B + r * RB + ks * 32 + ((lane >> 3) & 1) * 16;
                LDSM4(rbh[np], bd);
                LDSM4(rbl[np], bd + TILE_B);
            }
#pragma unroll
            for (int mf = 0; mf < 4; mf++)
#pragma unroll
                for (int nf = 0; nf < 4; nf++)
                    MMA_OP(acc[mf][nf], rah[mf], rbh[nf >> 1][(nf & 1) * 2],
                           rbh[nf >> 1][(nf & 1) * 2 + 1]);
#pragma unroll
            for (int mf = 0; mf < 4; mf++)
#pragma unroll
                for (int nf = 0; nf < 4; nf++)
                    MMA_OP(acc[mf][nf], rah[mf], rbl[nf >> 1][(nf & 1) * 2],
                           rbl[nf >> 1][(nf & 1) * 2 + 1]);
#pragma unroll
            for (int mf = 0; mf < 4; mf++)
#pragma unroll
                for (int nf = 0; nf < 4; nf++)
                    MMA_OP(acc[mf][nf], ral[mf], rbh[nf >> 1][(nf & 1) * 2],
                           rbh[nf >> 1][(nf & 1) * 2 + 1]);
        }
        __syncthreads();
        buf ^= 1;
    }

    float* C = Cp + (size_t)(blockIdx.x / nCols) * 128 * N;
    const int mrow = lane >> 2, ncol = (lane & 3) * 2;
#pragma unroll
    for (int mf = 0; mf < 4; mf++) {
#pragma unroll
        for (int nf = 0; nf < 4; nf++) {
            int r  = wm * 64 + mf * 16 + mrow;
            int cc = col0 + wn * 32 + nf * 8 + ncol;
            *(float2*)(C + (size_t)r * N + cc) =
                make_float2(acc[mf][nf][0], acc[mf][nf][1]);
            *(float2*)(C + (size_t)(r + 8) * N + cc) =
                make_float2(acc[mf][nf][2], acc[mf][nf][3]);
        }
    }
#undef LOAD_STAGE
}

// ---------------------------------------------------------------------------
// Fused (512 threads): blocks 0..127: reduce spec partials + 16 ODEs +
// ws2 bf16 split. Blocks 128..191: pulse MLP.
// ---------------------------------------------------------------------------
__global__ __launch_bounds__(512) void soliton_pulse_kernel(
    const float* __restrict__ d_a, const float* __restrict__ d_b,
    const float* __restrict__ filt,
    const float* __restrict__ W1, const float* __restrict__ b1,
    const float* __restrict__ W2, const float* __restrict__ b2,
    float* __restrict__ out_resp, float* __restrict__ out_pulse)
{
    const int tid = threadIdx.x;
    if (blockIdx.x < 128) {
        const int m = blockIdx.x;
        const int b = m >> 5, k = m & 31;
        __shared__ __align__(16) float srow[3072];
        __shared__ float resp_s[16];

        const size_t SPL4 = 128 * 3072 / 4;
        const size_t rb4 = (size_t)m * 768;
        for (int idx = tid; idx < 768; idx += 512) {
            float4 a = make_float4(0.f, 0.f, 0.f, 0.f);
#pragma unroll
            for (int s = 0; s < SKS; s++) {
                float4 v = ((const float4*)g_spec_p)[s * SPL4 + rb4 + idx];
                a.x += v.x; a.y += v.y; a.z += v.z; a.w += v.w;
            }
            ((float4*)srow)[idx] = a;
        }
        __syncthreads();

        if (tid < 16) {
            const int h = tid;
            float dot = 0.f;
#pragma unroll
            for (int d = 0; d < 64; d++)
                dot = fmaf(srow[h * 64 + d], srow[1024 + h * 64 + d], dot);

            float f = 1.f / (1.f + expf(-filt[h * 32 + k]));
            float stim = dot * 0.125f * f;

            const float a = d_a[0], bb = d_b[0];
            float scale = fmaxf(fabsf(stim), 1e-6f);
            float sn = stim / scale;
            float I = (fabsf(stim) > 0.5f) ? sn : sn * 0.1f;
            float v = 0.f, w = 0.f;
            const float dt = 0.2f;
#pragma unroll
            for (int s = 0; s < 5; s++) {
                float dv = v - v * v * v * (1.f / 3.f) - w + I;
                float dw = (v + a - bb * w) * 10.f;
                v = fminf(fmaxf(v + dt * dv, -3.f), 3.f);
                w = fminf(fmaxf(w + dt * dw, -3.f), 3.f);
            }
            float resp = v * scale;
            resp_s[h] = resp;
            out_resp[b * 512 + h * 32 + k] = resp;
        }
        __syncthreads();

        if (tid < 256) {
            const int h = tid >> 4;
            float r = resp_s[h];
            float4 vv = ((const float4*)srow)[512 + tid];
            float wv[4] = { r * vv.x, r * vv.y, r * vv.z, r * vv.w };
            ((uint2*)g_wshi)[(size_t)m * 256 + tid] = pack_hilo4(wv, false);
            ((uint2*)g_wslo)[(size_t)m * 256 + tid] = pack_hilo4(wv, true);
        }
    } else {
        const int bh = blockIdx.x - 128;
        const int b = bh >> 4, h = bh & 15;
        if (tid >= 32) return;
        const float* qm = g_qm + b * 1024 + h * 64;
        float acc = b1[tid];
#pragma unroll
        for (int dd = 0; dd < 64; dd++)
            acc = fmaf(qm[dd] * (1.0f / Tc), W1[tid * 64 + dd], acc);
        float h1 = acc / (1.f + expf(-acc));
        float pp = h1 * W2[tid];
#pragma unroll
        for (int off = 16; off; off >>= 1)
            pp += __shfl_down_sync(0xffffffffu, pp, off);
        if (tid == 0) {
            float xv = pp + b2[0];
            float sp = (xv > 20.f) ? xv : log1pf(expf(xv));
            out_pulse[bh] = 4.0f + sp;
        }
    }
}

// ---------------------------------------------------------------------------
// Reduce Z partials -> Zt (transposed, bf16 hi/lo): Zt[b][d][k] = Z[b*32+k][d]
// ---------------------------------------------------------------------------
__global__ void reduce_Zt()
{
    int i = blockIdx.x * blockDim.x + threadIdx.x;
    if (i >= 32768) return;
    const int m = i >> 8, d0 = (i & 255) * 4;
    const int b = m >> 5, k = m & 31;
    float4 a = make_float4(0.f, 0.f, 0.f, 0.f);
#pragma unroll
    for (int s = 0; s < SKZ; s++) {
        float4 v = ((const float4*)g_Zp)[(size_t)s * 32768 + i];
        a.x += v.x; a.y += v.y; a.z += v.z; a.w += v.w;
    }
    float vv[4] = { a.x, a.y, a.z, a.w };
#pragma unroll
    for (int j = 0; j < 4; j++) {
        __nv_bfloat16 hh = __float2bfloat16_rn(vv[j]);
        __nv_bfloat16 ll = __float2bfloat16_rn(vv[j] - __bfloat162float(hh));
        size_t oi = ((size_t)b * 1024 + d0 + j) * 32 + k;
        g_Zthi[oi] = hh;
        g_Ztlo[oi] = ll;
    }
}

// ---------------------------------------------------------------------------
// out HMMA: out[b, t0:t0+128, d0:d0+128] = sb[b,t,:] @ Zt[b,d,:]^T  (K=32)
// ---------------------------------------------------------------------------
__global__ __launch_bounds__(256, 2) void out_mma_kernel(float* __restrict__ out)
{
    __shared__ __align__(16) char smem[4 * TILE_B];
    const int tid = threadIdx.x, wid = tid >> 5, lane = tid & 31;
    const int t0 = blockIdx.x * 128, d0 = blockIdx.y * 128, b = blockIdx.z;
    const int wm = wid >> 2, wn = wid & 3;
    const uint32_t sbase = smem_u32(smem);

    {
        const char* srcs[4] = {
            (const char*)(g_sbhi + ((size_t)b * Tc + t0) * 32),
            (const char*)(g_sblo + ((size_t)b * Tc + t0) * 32),
            (const char*)(g_Zthi + ((size_t)b * 1024 + d0) * 32),
            (const char*)(g_Ztlo + ((size_t)b * 1024 + d0) * 32) };
#pragma unroll
        for (int a = 0; a < 4; a++) {
#pragma unroll
            for (int i = 0; i < 2; i++) {
                int e = tid + i * 256;
                int r = e >> 2, c = e & 3;
                uint4 v = *(const uint4*)(srcs[a] + (size_t)r * 64 + c * 16);
                *(uint4*)(smem + a * TILE_B + r * RB + c * 16) = v;
            }
        }
    }
    __syncthreads();

    float acc[4][4][4];
#pragma unroll
    for (int i = 0; i < 4; i++)
#pragma unroll
        for (int j = 0; j < 4; j++)
#pragma unroll
            for (int q = 0; q < 4; q++) acc[i][j][q] = 0.f;

#pragma unroll
    for (int ks = 0; ks < 2; ks++) {
        uint32_t rah[4][4], ral[4][4];
#pragma unroll
        for (int mf = 0; mf < 4; mf++) {
            int r = wm * 64 + mf * 16 + (lane & 15);
            uint32_t ad = sbase + r * RB + ks * 32 + ((lane >> 4) & 1) * 16;
            LDSM4(rah[mf], ad);
            LDSM4(ral[mf], ad + TILE_B);
        }
        uint32_t rbh[2][4], rbl[2][4];
#pragma unroll
        for (int np = 0; np < 2; np++) {
            int r = wn * 32 + (np * 2 + (lane >> 4)) * 8 + (lane & 7);
            uint32_t bd = sbase + 2 * TILE_B + r * RB + ks * 32 + ((lane >> 3) & 1) * 16;
            LDSM4(rbh[np], bd);
            LDSM4(rbl[np], bd + TILE_B);
        }
#pragma unroll
        for (int mf = 0; mf < 4; mf++)
#pragma unroll
            for (int nf = 0; nf < 4; nf++)
                MMA_OP(acc[mf][nf], rah[mf], rbh[nf >> 1][(nf & 1) * 2],
                       rbh[nf >> 1][(nf & 1) * 2 + 1]);
#pragma unroll
        for (int mf = 0; mf < 4; mf++)
#pragma unroll
            for (int nf = 0; nf < 4; nf++)
                MMA_OP(acc[mf][nf], rah[mf], rbl[nf >> 1][(nf & 1) * 2],
                       rbl[nf >> 1][(nf & 1) * 2 + 1]);
#pragma unroll
        for (int mf = 0; mf < 4; mf++)
#pragma unroll
            for (int nf = 0; nf < 4; nf++)
                MMA_OP(acc[mf][nf], ral[mf], rbh[nf >> 1][(nf & 1) * 2],
                       rbh[nf >> 1][(nf & 1) * 2 + 1]);
    }

    const int mrow = lane >> 2, ncol = (lane & 3) * 2;
#pragma unroll
    for (int mf = 0; mf < 4; mf++) {
#pragma unroll
        for (int nf = 0; nf < 4; nf++) {
            int r  = t0 + wm * 64 + mf * 16 + mrow;
            int cc = d0 + wn * 32 + nf * 8 + ncol;
            *(float2*)(out + ((size_t)b * Tc + r) * Dc + cc) =
                make_float2(acc[mf][nf][0], acc[mf][nf][1]);
            *(float2*)(out + ((size_t)b * Tc + r + 8) * Dc + cc) =
                make_float2(acc[mf][nf][2], acc[mf][nf][3]);
        }
    }
}

// ---------------------------------------------------------------------------
// Launch
// ---------------------------------------------------------------------------
extern "C" void kernel_launch(void* const* d_in, const int* in_sizes, int n_in,
                              void* d_out, int out_size)
{
    const float* x    = (const float*)d_in[0];
    const float* sb   = (const float*)d_in[1];
    const float* Wqkv = (const float*)d_in[2];
    const float* Wout = (const float*)d_in[3];
    const float* a    = (const float*)d_in[4];
    const float* b    = (const float*)d_in[5];
    const float* W1   = (const float*)d_in[6];
    const float* b1   = (const float*)d_in[7];
    const float* W2   = (const float*)d_in[8];
    const float* b2   = (const float*)d_in[9];
    const float* filt = (const float*)d_in[10];

    float* out       = (float*)d_out;
    float* out_pulse = out + (size_t)Bc * Tc * Dc;
    float* out_resp  = out_pulse + Bc * Hc;

    float *pspec_p, *pZp;
    cudaGetSymbolAddress((void**)&pspec_p, g_spec_p);
    cudaGetSymbolAddress((void**)&pZp, g_Zp);
    __nv_bfloat16 *pxshi, *pxslo, *pwqhi, *pwqlo, *pwohi, *pwolo, *pwshi, *pwslo;
    cudaGetSymbolAddress((void**)&pxshi, g_xshi);
    cudaGetSymbolAddress((void**)&pxslo, g_xslo);
    cudaGetSymbolAddress((void**)&pwqhi, g_wqhi);
    cudaGetSymbolAddress((void**)&pwqlo, g_wqlo);
    cudaGetSymbolAddress((void**)&pwohi, g_wohi);
    cudaGetSymbolAddress((void**)&pwolo, g_wolo);
    cudaGetSymbolAddress((void**)&pwshi, g_wshi);
    cudaGetSymbolAddress((void**)&pwslo, g_wslo);

    const int GEMM_SMEM = 2 * STAGE_B;
    cudaFuncSetAttribute(gemm_mma_sk, cudaFuncAttributeMaxDynamicSharedMemorySize,
                         GEMM_SMEM);

    // 1) xs partials (2 CTAs/SM tiling) + sb split + weight split (fused)
    xs_split_kernel<<<256 + 4096, 256>>>(x, sb, Wqkv, Wout);

    // 2) reduce -> xs bf16 hi/lo, xm fp32
    reduce_xs_xm<<<(32768 + 1024 + 255) / 256, 256>>>();

    // 3) spec partials [HMMA split-K 8] ++ qm GEMV fused
    gemm_mma_sk<<<24 * SKS + 512, 256, GEMM_SMEM>>>(
        pxshi, pxslo, pwqhi, pwqlo, pspec_p, 3072, 1024 / SKS, 24 * SKS, Wqkv);

    // 4) spec reduce + soliton + ws2 split + pulse MLP
    soliton_pulse_kernel<<<128 + 64, 512>>>(a, b, filt, W1, b1, W2, b2,
                                            out_resp, out_pulse);

    // 5) Z partials [HMMA split-K 16] + reduce -> Zt bf16
    gemm_mma_sk<<<8 * SKZ, 256, GEMM_SMEM>>>(
        pwshi, pwslo, pwohi, pwolo, pZp, 1024, 1024 / SKZ, 8 * SKZ, Wqkv);
    reduce_Zt<<<(32768 + 255) / 256, 256>>>();

    // 6) out = sb @ Zt^T [HMMA, K=32]
    out_mma_kernel<<<dim3(Tc / 128, Dc / 128, Bc), 256>>>(out);
}

// round 16
// speedup vs baseline: 2.1939x; 1.3575x over previous
#include <cuda_runtime.h>
#include <cuda_bf16.h>
#include <math.h>
#include <stdint.h>

// Problem constants
#define Bc  4
#define Tc  4096
#define Dc  1024
#define Hc  16
#define HDc 64
#define Kc  32

#define NS1 32      // t-slices for xs build (128 t each)
#define SKS 8       // split-K for spec GEMM (slab 128)
#define SKZ 16      // split-K for Z GEMM   (slab 64)

// ---------------- scratch (static device arrays) ----------------
__device__ float g_xs_p[NS1 * 128 * 1024];       // xs partials
__device__ float g_xm_p[NS1 * Bc * 1024];        // xmean partials
__device__ float g_xm[Bc * 1024];                // sum_t x
__device__ float g_qm[Bc * 1024];                // xm @ Wq^T (unnormalized)
__device__ float g_spec_p[SKS * 128 * 3072];     // spec GEMM partials
__device__ float g_Zp[SKZ * 128 * 1024];         // Z GEMM partials
__device__ __nv_bfloat16 g_xshi[128 * 1024], g_xslo[128 * 1024];
__device__ __nv_bfloat16 g_wqhi[3 * 1024 * 1024], g_wqlo[3 * 1024 * 1024];
__device__ __nv_bfloat16 g_wohi[1024 * 1024], g_wolo[1024 * 1024];
__device__ __nv_bfloat16 g_wshi[128 * 1024], g_wslo[128 * 1024];
__device__ __nv_bfloat16 g_sbhi[Bc * Tc * 32], g_sblo[Bc * Tc * 32];
__device__ __nv_bfloat16 g_Zthi[Bc * 1024 * 32], g_Ztlo[Bc * 1024 * 32];

__device__ __forceinline__ uint32_t smem_u32(const void* p) {
    uint32_t a;
    asm("{ .reg .u64 t; cvta.to.shared.u64 t, %1; cvt.u32.u64 %0, t; }"
        : "=r"(a) : "l"(p));
    return a;
}
__device__ __forceinline__ uint2 pack_hilo4(const float* v, bool lo) {
    __nv_bfloat16 h[4];
#pragma unroll
    for (int j = 0; j < 4; j++) {
        __nv_bfloat16 hh = __float2bfloat16_rn(v[j]);
        h[j] = lo ? __float2bfloat16_rn(v[j] - __bfloat162float(hh)) : hh;
    }
    uint2 r;
    r.x = (uint32_t)__bfloat16_as_ushort(h[0]) |
          ((uint32_t)__bfloat16_as_ushort(h[1]) << 16);
    r.y = (uint32_t)__bfloat16_as_ushort(h[2]) |
          ((uint32_t)__bfloat16_as_ushort(h[3]) << 16);
    return r;
}

// packed f32x2 helpers (FFMA2 path, sm_100+ PTX)
__device__ __forceinline__ unsigned long long splat2(float v) {
    unsigned long long r;
    asm("mov.b64 %0, {%1, %1};" : "=l"(r) : "f"(v));
    return r;
}
#define FMA2(acc, a, b)                                                       \
    asm("fma.rn.f32x2 %0, %1, %2, %0;" : "+l"(acc) : "l"(a), "l"(b))
#define UNPACK2(lo, hi, v)                                                    \
    asm("mov.b64 {%0, %1}, %2;" : "=f"(lo), "=f"(hi) : "l"(v))

#define MMA_OP(d, A, b0, b1)                                                  \
    asm volatile("mma.sync.aligned.m16n8k16.row.col.f32.bf16.bf16.f32 "       \
                 "{%0,%1,%2,%3},{%4,%5,%6,%7},{%8,%9},{%0,%1,%2,%3};"         \
                 : "+f"(d[0]), "+f"(d[1]), "+f"(d[2]), "+f"(d[3])             \
                 : "r"(A[0]), "r"(A[1]), "r"(A[2]), "r"(A[3]),                \
                   "r"(b0), "r"(b1))

#define LDSM4(r, addr)                                                        \
    asm volatile("ldmatrix.sync.aligned.m8n8.x4.shared.b16 {%0,%1,%2,%3},[%4];"\
        : "=r"((r)[0]), "=r"((r)[1]), "=r"((r)[2]), "=r"((r)[3]) : "r"(addr))

// ---------------------------------------------------------------------------
// K1 fused: blocks [0,256): xs partials + xm partials + sb bf16 split.
//   decode: b = bid>>6, s = (bid>>1)&31, dh = bid&1; thread owns 2 d's.
//   Inner loop on FFMA2 (fma.rn.f32x2): k-adjacent accumulator pairs,
//   sbs pairs loaded with ld.shared.v2.u64 (broadcast, conflict-free).
// Blocks [256, 256+4096): Wqkv/Wout bf16 hi/lo split.
// ---------------------------------------------------------------------------
__global__ __launch_bounds__(256, 2) void xs_split_kernel(
    const float* __restrict__ x, const float* __restrict__ sb,
    const float* __restrict__ Wqkv, const float* __restrict__ Wout)
{
    const int tid = threadIdx.x;
    if ((int)blockIdx.x >= 256) {
        int i = (blockIdx.x - 256) * 256 + tid;
        const int NQ4 = 3 * 1024 * 1024 / 4;
        const float* src;
        __nv_bfloat16 *hi, *lo;
        int j;
        if (i < NQ4) { src = Wqkv; hi = g_wqhi; lo = g_wqlo; j = i; }
        else { src = Wout; hi = g_wohi; lo = g_wolo; j = i - NQ4;
               if (j >= 1024 * 1024 / 4) return; }
        float4 v = ((const float4*)src)[j];
        float vv[4] = { v.x, v.y, v.z, v.w };
        ((uint2*)hi)[j] = pack_hilo4(vv, false);
        ((uint2*)lo)[j] = pack_hilo4(vv, true);
        return;
    }

    const int b = blockIdx.x >> 6;
    const int s = (blockIdx.x >> 1) & 31;
    const int dh = blockIdx.x & 1;
    const int d0 = dh * 512 + tid * 2;
    const int t0 = s * 128;

    __shared__ __align__(16) float sbs[128][32];
    {
        int e = tid;
#pragma unroll
        for (int i = 0; i < 4; i++, e += 256) {
            int tt = e >> 3, k4 = (e & 7) * 4;
            size_t gofs = ((size_t)b * Tc + t0 + tt) * 32 + k4;
            float4 v = *(const float4*)(sb + gofs);
            *(float4*)&sbs[tt][k4] = v;
            if (dh == 0) {
                float vv[4] = { v.x, v.y, v.z, v.w };
                ((uint2*)g_sbhi)[gofs / 4] = pack_hilo4(vv, false);
                ((uint2*)g_sblo)[gofs / 4] = pack_hilo4(vv, true);
            }
        }
    }
    __syncthreads();

    // 16 k-pairs x 2 d accumulators, packed f32x2 (zero bits == (0.f, 0.f))
    unsigned long long acc2[16][2];
#pragma unroll
    for (int p = 0; p < 16; p++) { acc2[p][0] = 0ull; acc2[p][1] = 0ull; }
    float am0 = 0.f, am1 = 0.f;

    const uint32_t sbs_base = smem_u32(&sbs[0][0]);
    const float* xb = x + ((size_t)b * Tc + t0) * Dc + d0;
    for (int t = 0; t < 128; t++) {
        float2 xv = *(const float2*)(xb + (size_t)t * Dc);
        am0 += xv.x; am1 += xv.y;
        unsigned long long bx = splat2(xv.x);
        unsigned long long by = splat2(xv.y);
        const uint32_t rowa = sbs_base + t * 128;
#pragma unroll
        for (int q = 0; q < 8; q++) {
            unsigned long long p0, p1;
            asm("ld.shared.v2.u64 {%0,%1},[%2];"
                : "=l"(p0), "=l"(p1) : "r"(rowa + q * 16));
            FMA2(acc2[q * 2][0], p0, bx);
            FMA2(acc2[q * 2][1], p0, by);
            FMA2(acc2[q * 2 + 1][0], p1, bx);
            FMA2(acc2[q * 2 + 1][1], p1, by);
        }
    }

    float* op = g_xs_p + (size_t)s * 131072 + (size_t)b * 32 * 1024 + d0;
#pragma unroll
    for (int p = 0; p < 16; p++) {
        float k0d0, k1d0, k0d1, k1d1;
        UNPACK2(k0d0, k1d0, acc2[p][0]);
        UNPACK2(k0d1, k1d1, acc2[p][1]);
        *(float2*)(op + (2 * p) * 1024)     = make_float2(k0d0, k0d1);
        *(float2*)(op + (2 * p + 1) * 1024) = make_float2(k1d0, k1d1);
    }
    *(float2*)(g_xm_p + (size_t)s * 4096 + b * 1024 + d0) =
        make_float2(am0, am1);
}

// ---------------------------------------------------------------------------
// Reduce xs partials -> bf16 hi/lo; xm partials -> fp32.
// ---------------------------------------------------------------------------
__global__ void reduce_xs_xm()
{
    int i = blockIdx.x * blockDim.x + threadIdx.x;
    if (i < 32768) {
        float4 a = make_float4(0.f, 0.f, 0.f, 0.f);
#pragma unroll 4
        for (int s = 0; s < NS1; s++) {
            float4 v = ((const float4*)g_xs_p)[(size_t)s * 32768 + i];
            a.x += v.x; a.y += v.y; a.z += v.z; a.w += v.w;
        }
        float vv[4] = { a.x, a.y, a.z, a.w };
        ((uint2*)g_xshi)[i] = pack_hilo4(vv, false);
        ((uint2*)g_xslo)[i] = pack_hilo4(vv, true);
    } else if (i < 32768 + 1024) {
        int j = i - 32768;
        float4 a = make_float4(0.f, 0.f, 0.f, 0.f);
#pragma unroll 4
        for (int s = 0; s < NS1; s++) {
            float4 v = ((const float4*)g_xm_p)[(size_t)s * 1024 + j];
            a.x += v.x; a.y += v.y; a.z += v.z; a.w += v.w;
        }
        ((float4*)g_xm)[j] = a;
    }
}

// ---------------------------------------------------------------------------
// HMMA GEMM NT, M=128, split-K, 3-product bf16 split + fused qm GEMV blocks.
// ---------------------------------------------------------------------------
#define KT      32
#define RB      80
#define TILE_B  (128 * RB)
#define STAGE_B (4 * TILE_B)

__global__ void __launch_bounds__(256, 2) gemm_mma_sk(
    const __nv_bfloat16* __restrict__ Ahi, const __nv_bfloat16* __restrict__ Alo,
    const __nv_bfloat16* __restrict__ Bhi, const __nv_bfloat16* __restrict__ Blo,
    float* __restrict__ Cp, int N, int kPerSplit, int nGemm,
    const float* __restrict__ WqF)
{
    const int tid = threadIdx.x;
    if ((int)blockIdx.x >= nGemm) {
        const int w = (blockIdx.x - nGemm) * 8 + (tid >> 5);
        const int lane = tid & 31;
        const int b = w >> 10, o = w & 1023;
        const float4* xm = (const float4*)(g_xm + b * 1024);
        const float4* wr = (const float4*)(WqF + (size_t)o * 1024);
        float s = 0.f;
#pragma unroll
        for (int j = 0; j < 8; j++) {
            float4 a = xm[lane + j * 32];
            float4 c = wr[lane + j * 32];
            s = fmaf(a.x, c.x, s); s = fmaf(a.y, c.y, s);
            s = fmaf(a.z, c.z, s); s = fmaf(a.w, c.w, s);
        }
#pragma unroll
        for (int off = 16; off; off >>= 1)
            s += __shfl_down_sync(0xffffffffu, s, off);
        if (lane == 0) g_qm[b * 1024 + o] = s;
        return;
    }

    extern __shared__ char smem[];
    const int Kd = 1024;
    const uint32_t sbase = smem_u32(smem);
    const int wid = tid >> 5, lane = tid & 31;
    const int nCols = N >> 7;
    const int col0 = (blockIdx.x % nCols) * 128;
    const int kb = (blockIdx.x / nCols) * kPerSplit;
    const int wm = wid >> 2, wn = wid & 3;

    const __nv_bfloat16* s0 = Ahi + kb;
    const __nv_bfloat16* s1 = Alo + kb;
    const __nv_bfloat16* s2 = Bhi + (size_t)col0 * Kd + kb;
    const __nv_bfloat16* s3 = Blo + (size_t)col0 * Kd + kb;

    const int r0c = tid >> 2, c0c = tid & 3;
    const int r1c = (tid + 256) >> 2, c1c = (tid + 256) & 3;

#define LOAD_STAGE(kt, buf)                                                   \
    do {                                                                      \
        uint32_t db = sbase + (buf) * STAGE_B;                                \
        const __nv_bfloat16* srcs[4] = { s0, s1, s2, s3 };                    \
        _Pragma("unroll")                                                     \
        for (int a = 0; a < 4; a++) {                                         \
            const char* g0 = (const char*)(srcs[a] + (size_t)r0c * Kd + (kt) * KT) + c0c * 16; \
            const char* g1 = (const char*)(srcs[a] + (size_t)r1c * Kd + (kt) * KT) + c1c * 16; \
            uint32_t p0 = db + a * TILE_B + r0c * RB + c0c * 16;              \
            uint32_t p1 = db + a * TILE_B + r1c * RB + c1c * 16;              \
            asm volatile("cp.async.cg.shared.global [%0],[%1],16;" :: "r"(p0), "l"(g0)); \
            asm volatile("cp.async.cg.shared.global [%0],[%1],16;" :: "r"(p1), "l"(g1)); \
        }                                                                     \
        asm volatile("cp.async.commit_group;");                               \
    } while (0)

    float acc[4][4][4];
#pragma unroll
    for (int i = 0; i < 4; i++)
#pragma unroll
        for (int j = 0; j < 4; j++)
#pragma unroll
            for (int q = 0; q < 4; q++) acc[i][j][q] = 0.f;

    LOAD_STAGE(0, 0);
    int buf = 0;
    const int nTiles = kPerSplit / KT;

    for (int kt = 0; kt < nTiles; kt++) {
        asm volatile("cp.async.wait_group 0;");
        __syncthreads();
        if (kt + 1 < nTiles) LOAD_STAGE(kt + 1, buf ^ 1);

        const uint32_t db = sbase + buf * STAGE_B;
#pragma unroll
        for (int ks = 0; ks < 2; ks++) {
            uint32_t rah[4][4], ral[4][4];
#pragma unroll
            for (int mf = 0; mf < 4; mf++) {
                int r = wm * 64 + mf * 16 + (lane & 15);
                uint32_t ad = db + r * RB + ks * 32 + ((lane >> 4) & 1) * 16;
                LDSM4(rah[mf], ad);
                LDSM4(ral[mf], ad + TILE_B);
            }
            uint32_t rbh[2][4], rbl[2][4];
#pragma unroll
            for (int np = 0; np < 2; np++) {
                int r = wn * 32 + (np * 2 + (lane >> 4)) * 8 + (lane & 7);
                uint32_t bd = db + 2 * TILE_B + r * RB + ks * 32 + ((lane >> 3) & 1) * 16;
                LDSM4(rbh[np], bd);
                LDSM4(rbl[np], bd + TILE_B);
            }
#pragma unroll
            for (int mf = 0; mf < 4; mf++)
#pragma unroll
                for (int nf = 0; nf < 4; nf++)
                    MMA_OP(acc[mf][nf], rah[mf], rbh[nf >> 1][(nf & 1) * 2],
                           rbh[nf >> 1][(nf & 1) * 2 + 1]);
#pragma unroll
            for (int mf = 0; mf < 4; mf++)
#pragma unroll
                for (int nf = 0; nf < 4; nf++)
                    MMA_OP(acc[mf][nf], rah[mf], rbl[nf >> 1][(nf & 1) * 2],
                           rbl[nf >> 1][(nf & 1) * 2 + 1]);
#pragma unroll
            for (int mf = 0; mf < 4; mf++)
#pragma unroll
                for (int nf = 0; nf < 4; nf++)
                    MMA_OP(acc[mf][nf], ral[mf], rbh[nf >> 1][(nf & 1) * 2],
                           rbh[nf >> 1][(nf & 1) * 2 + 1]);
        }
        __syncthreads();
        buf ^= 1;
    }

    float* C = Cp + (size_t)(blockIdx.x / nCols) * 128 * N;
    const int mrow = lane >> 2, ncol = (lane & 3) * 2;
#pragma unroll
    for (int mf = 0; mf < 4; mf++) {
#pragma unroll
        for (int nf = 0; nf < 4; nf++) {
            int r  = wm * 64 + mf * 16 + mrow;
            int cc = col0 + wn * 32 + nf * 8 + ncol;
            *(float2*)(C + (size_t)r * N + cc) =
                make_float2(acc[mf][nf][0], acc[mf][nf][1]);
            *(float2*)(C + (size_t)(r + 8) * N + cc) =
                make_float2(acc[mf][nf][2], acc[mf][nf][3]);
        }
    }
#undef LOAD_STAGE
}

// ---------------------------------------------------------------------------
// Fused (512 threads): blocks 0..127: reduce spec partials + 16 ODEs +
// ws2 bf16 split. Blocks 128..191: pulse MLP.
// ---------------------------------------------------------------------------
__global__ __launch_bounds__(512) void soliton_pulse_kernel(
    const float* __restrict__ d_a, const float* __restrict__ d_b,
    const float* __restrict__ filt,
    const float* __restrict__ W1, const float* __restrict__ b1,
    const float* __restrict__ W2, const float* __restrict__ b2,
    float* __restrict__ out_resp, float* __restrict__ out_pulse)
{
    const int tid = threadIdx.x;
    if (blockIdx.x < 128) {
        const int m = blockIdx.x;
        const int b = m >> 5, k = m & 31;
        __shared__ __align__(16) float srow[3072];
        __shared__ float resp_s[16];

        const size_t SPL4 = 128 * 3072 / 4;
        const size_t rb4 = (size_t)m * 768;
        for (int idx = tid; idx < 768; idx += 512) {
            float4 a = make_float4(0.f, 0.f, 0.f, 0.f);
#pragma unroll
            for (int s = 0; s < SKS; s++) {
                float4 v = ((const float4*)g_spec_p)[s * SPL4 + rb4 + idx];
                a.x += v.x; a.y += v.y; a.z += v.z; a.w += v.w;
            }
            ((float4*)srow)[idx] = a;
        }
        __syncthreads();

        if (tid < 16) {
            const int h = tid;
            float dot = 0.f;
#pragma unroll
            for (int d = 0; d < 64; d++)
                dot = fmaf(srow[h * 64 + d], srow[1024 + h * 64 + d], dot);

            float f = 1.f / (1.f + expf(-filt[h * 32 + k]));
            float stim = dot * 0.125f * f;

            const float a = d_a[0], bb = d_b[0];
            float scale = fmaxf(fabsf(stim), 1e-6f);
            float sn = stim / scale;
            float I = (fabsf(stim) > 0.5f) ? sn : sn * 0.1f;
            float v = 0.f, w = 0.f;
            const float dt = 0.2f;
#pragma unroll
            for (int s = 0; s < 5; s++) {
                float dv = v - v * v * v * (1.f / 3.f) - w + I;
                float dw = (v + a - bb * w) * 10.f;
                v = fminf(fmaxf(v + dt * dv, -3.f), 3.f);
                w = fminf(fmaxf(w + dt * dw, -3.f), 3.f);
            }
            float resp = v * scale;
            resp_s[h] = resp;
            out_resp[b * 512 + h * 32 + k] = resp;
        }
        __syncthreads();

        if (tid < 256) {
            const int h = tid >> 4;
            float r = resp_s[h];
            float4 vv = ((const float4*)srow)[512 + tid];
            float wv[4] = { r * vv.x, r * vv.y, r * vv.z, r * vv.w };
            ((uint2*)g_wshi)[(size_t)m * 256 + tid] = pack_hilo4(wv, false);
            ((uint2*)g_wslo)[(size_t)m * 256 + tid] = pack_hilo4(wv, true);
        }
    } else {
        const int bh = blockIdx.x - 128;
        const int b = bh >> 4, h = bh & 15;
        if (tid >= 32) return;
        const float* qm = g_qm + b * 1024 + h * 64;
        float acc = b1[tid];
#pragma unroll
        for (int dd = 0; dd < 64; dd++)
            acc = fmaf(qm[dd] * (1.0f / Tc), W1[tid * 64 + dd], acc);
        float h1 = acc / (1.f + expf(-acc));
        float pp = h1 * W2[tid];
#pragma unroll
        for (int off = 16; off; off >>= 1)
            pp += __shfl_down_sync(0xffffffffu, pp, off);
        if (tid == 0) {
            float xv = pp + b2[0];
            float sp = (xv > 20.f) ? xv : log1pf(expf(xv));
            out_pulse[bh] = 4.0f + sp;
        }
    }
}

// ---------------------------------------------------------------------------
// Reduce Z partials -> Zt (transposed, bf16 hi/lo): Zt[b][d][k] = Z[b*32+k][d]
// ---------------------------------------------------------------------------
__global__ void reduce_Zt()
{
    int i = blockIdx.x * blockDim.x + threadIdx.x;
    if (i >= 32768) return;
    const int m = i >> 8, d0 = (i & 255) * 4;
    const int b = m >> 5, k = m & 31;
    float4 a = make_float4(0.f, 0.f, 0.f, 0.f);
#pragma unroll
    for (int s = 0; s < SKZ; s++) {
        float4 v = ((const float4*)g_Zp)[(size_t)s * 32768 + i];
        a.x += v.x; a.y += v.y; a.z += v.z; a.w += v.w;
    }
    float vv[4] = { a.x, a.y, a.z, a.w };
#pragma unroll
    for (int j = 0; j < 4; j++) {
        __nv_bfloat16 hh = __float2bfloat16_rn(vv[j]);
        __nv_bfloat16 ll = __float2bfloat16_rn(vv[j] - __bfloat162float(hh));
        size_t oi = ((size_t)b * 1024 + d0 + j) * 32 + k;
        g_Zthi[oi] = hh;
        g_Ztlo[oi] = ll;
    }
}

// ---------------------------------------------------------------------------
// out HMMA: out[b, t0:t0+128, d0:d0+128] = sb[b,t,:] @ Zt[b,d,:]^T  (K=32)
// ---------------------------------------------------------------------------
__global__ __launch_bounds__(256, 2) void out_mma_kernel(float* __restrict__ out)
{
    __shared__ __align__(16) char smem[4 * TILE_B];
    const int tid = threadIdx.x, wid = tid >> 5, lane = tid & 31;
    const int t0 = blockIdx.x * 128, d0 = blockIdx.y * 128, b = blockIdx.z;
    const int wm = wid >> 2, wn = wid & 3;
    const uint32_t sbase = smem_u32(smem);

    {
        const char* srcs[4] = {
            (const char*)(g_sbhi + ((size_t)b * Tc + t0) * 32),
            (const char*)(g_sblo + ((size_t)b * Tc + t0) * 32),
            (const char*)(g_Zthi + ((size_t)b * 1024 + d0) * 32),
            (const char*)(g_Ztlo + ((size_t)b * 1024 + d0) * 32) };
#pragma unroll
        for (int a = 0; a < 4; a++) {
#pragma unroll
            for (int i = 0; i < 2; i++) {
                int e = tid + i * 256;
                int r = e >> 2, c = e & 3;
                uint4 v = *(const uint4*)(srcs[a] + (size_t)r * 64 + c * 16);
                *(uint4*)(smem + a * TILE_B + r * RB + c * 16) = v;
            }
        }
    }
    __syncthreads();

    float acc[4][4][4];
#pragma unroll
    for (int i = 0; i < 4; i++)
#pragma unroll
        for (int j = 0; j < 4; j++)
#pragma unroll
            for (int q = 0; q < 4; q++) acc[i][j][q] = 0.f;

#pragma unroll
    for (int ks = 0; ks < 2; ks++) {
        uint32_t rah[4][4], ral[4][4];
#pragma unroll
        for (int mf = 0; mf < 4; mf++) {
            int r = wm * 64 + mf * 16 + (lane & 15);
            uint32_t ad = sbase + r * RB + ks * 32 + ((lane >> 4) & 1) * 16;
            LDSM4(rah[mf], ad);
            LDSM4(ral[mf], ad + TILE_B);
        }
        uint32_t rbh[2][4], rbl[2][4];
#pragma unroll
        for (int np = 0; np < 2; np++) {
            int r = wn * 32 + (np * 2 + (lane >> 4)) * 8 + (lane & 7);
            uint32_t bd = sbase + 2 * TILE_B + r * RB + ks * 32 + ((lane >> 3) & 1) * 16;
            LDSM4(rbh[np], bd);
            LDSM4(rbl[np], bd + TILE_B);
        }
#pragma unroll
        for (int mf = 0; mf < 4; mf++)
#pragma unroll
            for (int nf = 0; nf < 4; nf++)
                MMA_OP(acc[mf][nf], rah[mf], rbh[nf >> 1][(nf & 1) * 2],
                       rbh[nf >> 1][(nf & 1) * 2 + 1]);
#pragma unroll
        for (int mf = 0; mf < 4; mf++)
#pragma unroll
            for (int nf = 0; nf < 4; nf++)
                MMA_OP(acc[mf][nf], rah[mf], rbl[nf >> 1][(nf & 1) * 2],
                       rbl[nf >> 1][(nf & 1) * 2 + 1]);
#pragma unroll
        for (int mf = 0; mf < 4; mf++)
#pragma unroll
            for (int nf = 0; nf < 4; nf++)
                MMA_OP(acc[mf][nf], ral[mf], rbh[nf >> 1][(nf & 1) * 2],
                       rbh[nf >> 1][(nf & 1) * 2 + 1]);
    }

    const int mrow = lane >> 2, ncol = (lane & 3) * 2;
#pragma unroll
    for (int mf = 0; mf < 4; mf++) {
#pragma unroll
        for (int nf = 0; nf < 4; nf++) {
            int r  = t0 + wm * 64 + mf * 16 + mrow;
            int cc = d0 + wn * 32 + nf * 8 + ncol;
            *(float2*)(out + ((size_t)b * Tc + r) * Dc + cc) =
                make_float2(acc[mf][nf][0], acc[mf][nf][1]);
            *(float2*)(out + ((size_t)b * Tc + r + 8) * Dc + cc) =
                make_float2(acc[mf][nf][2], acc[mf][nf][3]);
        }
    }
}

// ---------------------------------------------------------------------------
// Launch
// ---------------------------------------------------------------------------
extern "C" void kernel_launch(void* const* d_in, const int* in_sizes, int n_in,
                              void* d_out, int out_size)
{
    const float* x    = (const float*)d_in[0];
    const float* sb   = (const float*)d_in[1];
    const float* Wqkv = (const float*)d_in[2];
    const float* Wout = (const float*)d_in[3];
    const float* a    = (const float*)d_in[4];
    const float* b    = (const float*)d_in[5];
    const float* W1   = (const float*)d_in[6];
    const float* b1   = (const float*)d_in[7];
    const float* W2   = (const float*)d_in[8];
    const float* b2   = (const float*)d_in[9];
    const float* filt = (const float*)d_in[10];

    float* out       = (float*)d_out;
    float* out_pulse = out + (size_t)Bc * Tc * Dc;
    float* out_resp  = out_pulse + Bc * Hc;

    float *pspec_p, *pZp;
    cudaGetSymbolAddress((void**)&pspec_p, g_spec_p);
    cudaGetSymbolAddress((void**)&pZp, g_Zp);
    __nv_bfloat16 *pxshi, *pxslo, *pwqhi, *pwqlo, *pwohi, *pwolo, *pwshi, *pwslo;
    cudaGetSymbolAddress((void**)&pxshi, g_xshi);
    cudaGetSymbolAddress((void**)&pxslo, g_xslo);
    cudaGetSymbolAddress((void**)&pwqhi, g_wqhi);
    cudaGetSymbolAddress((void**)&pwqlo, g_wqlo);
    cudaGetSymbolAddress((void**)&pwohi, g_wohi);
    cudaGetSymbolAddress((void**)&pwolo, g_wolo);
    cudaGetSymbolAddress((void**)&pwshi, g_wshi);
    cudaGetSymbolAddress((void**)&pwslo, g_wslo);

    const int GEMM_SMEM = 2 * STAGE_B;
    cudaFuncSetAttribute(gemm_mma_sk, cudaFuncAttributeMaxDynamicSharedMemorySize,
                         GEMM_SMEM);

    // 1) xs partials (FFMA2 inner loop) + sb split + weight split (fused)
    xs_split_kernel<<<256 + 4096, 256>>>(x, sb, Wqkv, Wout);

    // 2) reduce -> xs bf16 hi/lo, xm fp32
    reduce_xs_xm<<<(32768 + 1024 + 255) / 256, 256>>>();

    // 3) spec partials [HMMA split-K 8] ++ qm GEMV fused
    gemm_mma_sk<<<24 * SKS + 512, 256, GEMM_SMEM>>>(
        pxshi, pxslo, pwqhi, pwqlo, pspec_p, 3072, 1024 / SKS, 24 * SKS, Wqkv);

    // 4) spec reduce + soliton + ws2 split + pulse MLP
    soliton_pulse_kernel<<<128 + 64, 512>>>(a, b, filt, W1, b1, W2, b2,
                                            out_resp, out_pulse);

    // 5) Z partials [HMMA split-K 16] + reduce -> Zt bf16
    gemm_mma_sk<<<8 * SKZ, 256, GEMM_SMEM>>>(
        pwshi, pwslo, pwohi, pwolo, pZp, 1024, 1024 / SKZ, 8 * SKZ, Wqkv);
    reduce_Zt<<<(32768 + 255) / 256, 256>>>();

    // 6) out = sb @ Zt^T [HMMA, K=32]
    out_mma_kernel<<<dim3(Tc / 128, Dc / 128, Bc), 256>>>(out);
}